// round 1
// baseline (speedup 1.0000x reference)
#include <cuda_runtime.h>
#include <cuda_bf16.h>
#include <math.h>

#define BATCH 16
#define CHN   640
#define SP    4096    // 64*64
#define TT    77
#define XDIM  768
#define NHE   8
#define HDIM  80
#define INNER 640

// ---------------- scratch (device globals; no allocation) ----------------
__device__ float g_xn[(size_t)BATCH * CHN * SP];     // LN output, [b][c][s]
__device__ float g_q [(size_t)BATCH * SP * INNER];   // [b][s][n]
__device__ float g_k [(size_t)BATCH * TT * INNER];   // [b][t][n]
__device__ float g_v [(size_t)BATCH * TT * INNER];   // [b][t][n]
__device__ float g_at[(size_t)BATCH * SP * INNER];   // [b][s][n]

// ---------------- LayerNorm over channels ----------------
__global__ void __launch_bounds__(256) ln_kernel(const float* __restrict__ x,
                                                 const float* __restrict__ w,
                                                 const float* __restrict__ bia)
{
    int s = blockIdx.x * 256 + threadIdx.x;       // 0..4095
    int b = blockIdx.y;
    const float* xp = x + (size_t)b * CHN * SP + s;
    float sum = 0.f, sumsq = 0.f;
    for (int c = 0; c < CHN; c++) {
        float v = xp[(size_t)c * SP];
        sum += v; sumsq += v * v;
    }
    float mu  = sum * (1.0f / CHN);
    float var = sumsq * (1.0f / CHN) - mu * mu;
    float rstd = rsqrtf(var + 1e-6f);
    float* op = g_xn + (size_t)b * CHN * SP + s;
    for (int c = 0; c < CHN; c++) {
        float v = xp[(size_t)c * SP];
        op[(size_t)c * SP] = (v - mu) * rstd * w[c] + bia[c];
    }
}

// ---------------- tf32 MMA GEMM ----------------
#define BM 128
#define BN 128
#define BKK 16
#define PAD 136

__device__ __forceinline__ unsigned f2tf(float x)
{
    unsigned r;
    asm("cvt.rna.tf32.f32 %0, %1;" : "=r"(r) : "f"(x));
    return r;
}

__device__ __forceinline__ void mma_tf32(float c[4], unsigned a0, unsigned a1,
                                         unsigned a2, unsigned a3,
                                         unsigned b0, unsigned b1)
{
    asm volatile(
        "mma.sync.aligned.m16n8k8.row.col.f32.tf32.tf32.f32 "
        "{%0,%1,%2,%3},{%4,%5,%6,%7},{%8,%9},{%0,%1,%2,%3};"
        : "+f"(c[0]), "+f"(c[1]), "+f"(c[2]), "+f"(c[3])
        : "r"(a0), "r"(a1), "r"(a2), "r"(a3), "r"(b0), "r"(b1));
}

// ALOAD: 0 = A is the LN output in [b][c][s] layout (A(m=b*SP+s, k=c))
//        1 = A row-major [M][K]
// EPI:   0 = plain row-major store Cout[m*N + n]
//        1 = add bias[n], add residual, write transposed to [b][n][s]
template<int ALOAD, int EPI, bool MG>
__global__ void __launch_bounds__(256, 2)
gemm_tf32(const float* __restrict__ A, const float* __restrict__ Bw,
          float* __restrict__ Cout, int M, int N, int K,
          const float* __restrict__ bias, const float* __restrict__ resid)
{
    __shared__ float smem[2 * BKK * PAD];   // As | Bs, reused as Cs in epilogue
    float* As = smem;
    float* Bs = smem + BKK * PAD;

    int tid = threadIdx.x;
    int lane = tid & 31, w = tid >> 5;
    int wm = w & 3, wn = w >> 2;        // 4 warps in M, 2 in N
    int m0 = blockIdx.y * BM;
    int n0 = blockIdx.x * BN;
    int mb = wm * 32, nb = wn * 64;

    float acc[2][8][4];
#pragma unroll
    for (int i = 0; i < 2; i++)
#pragma unroll
        for (int j = 0; j < 8; j++)
#pragma unroll
            for (int l = 0; l < 4; l++) acc[i][j][l] = 0.f;

    const float* Abase = A;
    if (ALOAD == 0) {
        int b = m0 >> 12;           // SP = 4096, BM divides SP
        int s0 = m0 & (SP - 1);
        Abase = A + (size_t)b * CHN * SP + s0;
    }

    for (int k0 = 0; k0 < K; k0 += BKK) {
        if (ALOAD == 0) {
#pragma unroll
            for (int r = 0; r < 2; r++) {
                int idx = (r * 256 + tid) * 4;
                int kk = idx >> 7, mi = idx & 127;
                float4 v = *reinterpret_cast<const float4*>(
                    Abase + (size_t)(k0 + kk) * SP + mi);
                *reinterpret_cast<float4*>(&As[kk * PAD + mi]) = v;
            }
        } else {
#pragma unroll
            for (int hh = 0; hh < 2; hh++) {
                int mi = hh * 64 + (tid >> 2);
                int kk = (tid & 3) * 4;
                float4 v = make_float4(0.f, 0.f, 0.f, 0.f);
                if (!MG || (m0 + mi) < M)
                    v = *reinterpret_cast<const float4*>(
                        A + (size_t)(m0 + mi) * K + k0 + kk);
                As[(kk + 0) * PAD + mi] = v.x;
                As[(kk + 1) * PAD + mi] = v.y;
                As[(kk + 2) * PAD + mi] = v.z;
                As[(kk + 3) * PAD + mi] = v.w;
            }
        }
#pragma unroll
        for (int r = 0; r < 2; r++) {
            int idx = (r * 256 + tid) * 4;
            int kk = idx >> 7, nn = idx & 127;
            float4 v = *reinterpret_cast<const float4*>(
                Bw + (size_t)(k0 + kk) * N + n0 + nn);
            *reinterpret_cast<float4*>(&Bs[kk * PAD + nn]) = v;
        }
        __syncthreads();

#pragma unroll
        for (int kc = 0; kc < BKK; kc += 8) {
            int kr = kc + (lane & 3);
            unsigned a[2][4];
#pragma unroll
            for (int im = 0; im < 2; im++) {
                int mrow = mb + im * 16 + (lane >> 2);
                a[im][0] = f2tf(As[kr * PAD + mrow]);
                a[im][1] = f2tf(As[kr * PAD + mrow + 8]);
                a[im][2] = f2tf(As[(kr + 4) * PAD + mrow]);
                a[im][3] = f2tf(As[(kr + 4) * PAD + mrow + 8]);
            }
#pragma unroll
            for (int in_ = 0; in_ < 8; in_++) {
                int ncol = nb + in_ * 8 + (lane >> 2);
                unsigned b0 = f2tf(Bs[kr * PAD + ncol]);
                unsigned b1 = f2tf(Bs[(kr + 4) * PAD + ncol]);
#pragma unroll
                for (int im = 0; im < 2; im++)
                    mma_tf32(acc[im][in_], a[im][0], a[im][1], a[im][2],
                             a[im][3], b0, b1);
            }
        }
        __syncthreads();
    }

    // -------- epilogue (smem-staged for coalesced stores) --------
    float* Cs = smem;   // 32*132 = 4224 floats <= 4352 available
    if (EPI == 0) {
#pragma unroll 1
        for (int ch = 0; ch < 4; ch++) {        // chunks of 32 M-rows
            __syncthreads();
            if (wm == ch) {
#pragma unroll
                for (int im = 0; im < 2; im++) {
                    int r0 = im * 16 + (lane >> 2);
#pragma unroll
                    for (int in_ = 0; in_ < 8; in_++) {
                        int cc = nb + in_ * 8 + (lane & 3) * 2;
                        Cs[r0 * 132 + cc]           = acc[im][in_][0];
                        Cs[r0 * 132 + cc + 1]       = acc[im][in_][1];
                        Cs[(r0 + 8) * 132 + cc]     = acc[im][in_][2];
                        Cs[(r0 + 8) * 132 + cc + 1] = acc[im][in_][3];
                    }
                }
            }
            __syncthreads();
            for (int t = tid; t < 32 * 128; t += 256) {
                int ml = t >> 7, n = t & 127;
                int m = m0 + ch * 32 + ml;
                if (MG && m >= M) continue;
                Cout[(size_t)m * N + n0 + n] = Cs[ml * 132 + n];
            }
        }
    } else {
#pragma unroll 1
        for (int ch = 0; ch < 4; ch++) {        // chunks of 32 N-cols
            __syncthreads();
            if (wn == (ch >> 1)) {
                int inlo = (ch & 1) * 4;
#pragma unroll
                for (int im = 0; im < 2; im++) {
                    int mrow = mb + im * 16 + (lane >> 2);
#pragma unroll
                    for (int ii = 0; ii < 4; ii++) {
                        int in_ = inlo + ii;
                        int nl = in_ * 8 + (lane & 3) * 2 - (ch & 1) * 32;
                        Cs[nl * 132 + mrow]           = acc[im][in_][0];
                        Cs[(nl + 1) * 132 + mrow]     = acc[im][in_][1];
                        Cs[nl * 132 + mrow + 8]       = acc[im][in_][2];
                        Cs[(nl + 1) * 132 + mrow + 8] = acc[im][in_][3];
                    }
                }
            }
            __syncthreads();
            for (int t = tid; t < 32 * 128; t += 256) {
                int nl = t >> 7, ml = t & 127;
                int n = n0 + ch * 32 + nl;
                int m = m0 + ml;
                int b = m >> 12, s = m & (SP - 1);
                size_t addr = (size_t)b * CHN * SP + (size_t)n * SP + s;
                Cout[addr] = Cs[nl * 132 + ml] + bias[n] + resid[addr];
            }
        }
    }
}

// ---------------- fused attention (T=77, HD=80) ----------------
// One warp per query row; K stored d-major in smem for conflict-free dots.
__global__ void __launch_bounds__(256) attn_kernel()
{
    extern __shared__ float sm[];
    float* k_s = sm;                  // [80][77], k_s[d*77 + t]
    float* v_s = sm + 80 * TT;        // [77][80], v_s[t*80 + d]
    float* p_s = v_s + TT * HDIM;     // [8][80]

    int tid = threadIdx.x, lane = tid & 31, w = tid >> 5;
    int b = blockIdx.z, h = blockIdx.y;
    int s0 = blockIdx.x * 256;

    const float* kb = g_k + (size_t)b * TT * INNER + h * HDIM;
    const float* vb = g_v + (size_t)b * TT * INNER + h * HDIM;
    for (int idx = tid; idx < TT * HDIM; idx += 256) {
        int t = idx / HDIM, d = idx % HDIM;
        float kv = kb[(size_t)t * INNER + d];
        float vv = vb[(size_t)t * INNER + d];
        k_s[d * TT + t] = kv;
        v_s[t * HDIM + d] = vv;
    }
    __syncthreads();

    const float scale = 0.11180339887498949f;   // 1/sqrt(80)
    int t0 = lane, t1 = lane + 32;
    bool has2 = (lane < TT - 64);               // lane < 13
    int t2 = has2 ? lane + 64 : 0;
    int d0 = lane, d1 = lane + 32;
    bool hasd2 = (lane < HDIM - 64);            // lane < 16
    int d2 = hasd2 ? lane + 64 : 0;

    for (int it = 0; it < 32; it++) {
        int s = s0 + w * 32 + it;
        const float4* qp = reinterpret_cast<const float4*>(
            g_q + ((size_t)b * SP + s) * INNER + h * HDIM);
        float sc0 = 0.f, sc1 = 0.f, sc2 = 0.f;
#pragma unroll
        for (int d4 = 0; d4 < HDIM / 4; d4++) {
            float4 qv = qp[d4];
            float qa[4] = {qv.x, qv.y, qv.z, qv.w};
#pragma unroll
            for (int j = 0; j < 4; j++) {
                int d = d4 * 4 + j;
                sc0 += qa[j] * k_s[d * TT + t0];
                sc1 += qa[j] * k_s[d * TT + t1];
                sc2 += qa[j] * k_s[d * TT + t2];
            }
        }
        sc0 *= scale; sc1 *= scale; sc2 *= scale;
        if (!has2) sc2 = -1e30f;
        float mx = fmaxf(sc0, fmaxf(sc1, sc2));
#pragma unroll
        for (int off = 16; off; off >>= 1)
            mx = fmaxf(mx, __shfl_xor_sync(0xffffffffu, mx, off));
        float e0 = __expf(sc0 - mx), e1 = __expf(sc1 - mx);
        float e2 = has2 ? __expf(sc2 - mx) : 0.f;
        float sum = e0 + e1 + e2;
#pragma unroll
        for (int off = 16; off; off >>= 1)
            sum += __shfl_xor_sync(0xffffffffu, sum, off);
        float inv = 1.f / sum;
        p_s[w * 80 + t0] = e0 * inv;
        p_s[w * 80 + t1] = e1 * inv;
        if (has2) p_s[w * 80 + lane + 64] = e2 * inv;
        __syncwarp();

        float o0 = 0.f, o1 = 0.f, o2 = 0.f;
#pragma unroll 7
        for (int t = 0; t < TT; t++) {
            float p = p_s[w * 80 + t];
            o0 += p * v_s[t * HDIM + d0];
            o1 += p * v_s[t * HDIM + d1];
            o2 += p * v_s[t * HDIM + d2];
        }
        float* op = g_at + ((size_t)b * SP + s) * INNER + h * HDIM;
        op[d0] = o0;
        op[d1] = o1;
        if (hasd2) op[d2] = o2;
        __syncwarp();
    }
}

// ---------------- launch ----------------
extern "C" void kernel_launch(void* const* d_in, const int* in_sizes, int n_in,
                              void* d_out, int out_size)
{
    (void)in_sizes; (void)n_in; (void)out_size;
    const float* hs  = (const float*)d_in[0];
    const float* enc = (const float*)d_in[1];
    const float* lnw = (const float*)d_in[2];
    const float* lnb = (const float*)d_in[3];
    const float* wq  = (const float*)d_in[4];
    const float* wk  = (const float*)d_in[5];
    const float* wv  = (const float*)d_in[6];
    const float* wo  = (const float*)d_in[7];
    const float* bo  = (const float*)d_in[8];
    float* out = (float*)d_out;

    float *p_xn, *p_q, *p_k, *p_v, *p_at;
    cudaGetSymbolAddress((void**)&p_xn, g_xn);
    cudaGetSymbolAddress((void**)&p_q,  g_q);
    cudaGetSymbolAddress((void**)&p_k,  g_k);
    cudaGetSymbolAddress((void**)&p_v,  g_v);
    cudaGetSymbolAddress((void**)&p_at, g_at);

    int attn_smem = (80 * TT + TT * HDIM + 8 * 80) * (int)sizeof(float);
    cudaFuncSetAttribute(attn_kernel,
                         cudaFuncAttributeMaxDynamicSharedMemorySize, attn_smem);

    // 1. LayerNorm -> g_xn [b][c][s]
    ln_kernel<<<dim3(SP / 256, BATCH), 256>>>(hs, lnw, lnb);

    // 2. Q = xn @ wq  -> g_q [b*s][n]
    gemm_tf32<0, 0, false><<<dim3(INNER / BN, (BATCH * SP) / BM), 256>>>(
        p_xn, wq, p_q, BATCH * SP, INNER, CHN, nullptr, nullptr);

    // 3/4. K,V = enc @ wk / wv
    int mt_kv = (BATCH * TT + BM - 1) / BM;
    gemm_tf32<1, 0, true><<<dim3(INNER / BN, mt_kv), 256>>>(
        enc, wk, p_k, BATCH * TT, INNER, XDIM, nullptr, nullptr);
    gemm_tf32<1, 0, true><<<dim3(INNER / BN, mt_kv), 256>>>(
        enc, wv, p_v, BATCH * TT, INNER, XDIM, nullptr, nullptr);

    // 5. attention -> g_at
    attn_kernel<<<dim3(SP / 256, NHE, BATCH), 256, attn_smem>>>();

    // 6. out = attn @ wo + bo, +residual, transpose to [b][c][s]
    gemm_tf32<1, 1, false><<<dim3(CHN / BN, (BATCH * SP) / BM), 256>>>(
        p_at, wo, out, BATCH * SP, CHN, INNER, bo, hs);
}

// round 3
// speedup vs baseline: 1.0708x; 1.0708x over previous
#include <cuda_runtime.h>
#include <cuda_bf16.h>
#include <math.h>
#include <stdint.h>

#define BATCH 16
#define CHN   640
#define SP    4096
#define TT    77
#define XDIM  768
#define NHE   8
#define HDIM  80
#define INNER 640

// ---------------- scratch ----------------
__device__ float g_xn [(size_t)BATCH * CHN * SP];
__device__ float g_q  [(size_t)BATCH * SP * INNER];
__device__ float g_k  [(size_t)BATCH * TT * INNER];
__device__ float g_v  [(size_t)BATCH * TT * INNER];
__device__ float g_at [(size_t)BATCH * SP * INNER];
__device__ float g_wqt[(size_t)INNER * CHN];
__device__ float g_wkt[(size_t)INNER * XDIM];
__device__ float g_wvt[(size_t)INNER * XDIM];
__device__ float g_wot[(size_t)CHN * INNER];

// ---------------- helpers ----------------
__device__ __forceinline__ uint32_t smem_u32(const void* p) {
    uint32_t a;
    asm("{ .reg .u64 t; cvta.to.shared.u64 t, %1; cvt.u32.u64 %0, t; }"
        : "=r"(a) : "l"(p));
    return a;
}
__device__ __forceinline__ void cp16(uint32_t dst, const float* src, bool v) {
    int sz = v ? 16 : 0;
    asm volatile("cp.async.cg.shared.global [%0], [%1], 16, %2;"
                 :: "r"(dst), "l"(src), "r"(sz) : "memory");
}
#define CP_COMMIT() asm volatile("cp.async.commit_group;" ::: "memory")
#define CP_WAIT1()  asm volatile("cp.async.wait_group 1;" ::: "memory")
#define CP_WAIT0()  asm volatile("cp.async.wait_group 0;" ::: "memory")

__device__ __forceinline__ void mma_tf32(float c[4], unsigned a0, unsigned a1,
                                         unsigned a2, unsigned a3,
                                         unsigned b0, unsigned b1)
{
    asm volatile(
        "mma.sync.aligned.m16n8k8.row.col.f32.tf32.tf32.f32 "
        "{%0,%1,%2,%3},{%4,%5,%6,%7},{%8,%9},{%0,%1,%2,%3};"
        : "+f"(c[0]), "+f"(c[1]), "+f"(c[2]), "+f"(c[3])
        : "r"(a0), "r"(a1), "r"(a2), "r"(a3), "r"(b0), "r"(b1));
}

// ---------------- LayerNorm ----------------
__global__ void __launch_bounds__(256) ln_kernel(const float* __restrict__ x,
                                                 const float* __restrict__ w,
                                                 const float* __restrict__ bia)
{
    int s = blockIdx.x * 256 + threadIdx.x;
    int b = blockIdx.y;
    const float* xp = x + (size_t)b * CHN * SP + s;
    float sum = 0.f, sumsq = 0.f;
    for (int c = 0; c < CHN; c++) { float v = xp[(size_t)c * SP]; sum += v; sumsq += v * v; }
    float mu = sum * (1.0f / CHN);
    float var = sumsq * (1.0f / CHN) - mu * mu;
    float rstd = rsqrtf(var + 1e-6f);
    float* op = g_xn + (size_t)b * CHN * SP + s;
    for (int c = 0; c < CHN; c++) {
        float v = xp[(size_t)c * SP];
        op[(size_t)c * SP] = (v - mu) * rstd * w[c] + bia[c];
    }
}

// ---------------- weight transpose [R][C] -> [C][R] ----------------
__global__ void __launch_bounds__(256) transpose_k(const float* __restrict__ in,
                                                   float* __restrict__ out, int R, int C)
{
    __shared__ float t[32][33];
    int c0 = blockIdx.x * 32, r0 = blockIdx.y * 32;
    int x = threadIdx.x & 31, y = (threadIdx.x >> 5) * 4;
#pragma unroll
    for (int i = 0; i < 4; i++)
        t[y + i][x] = in[(size_t)(r0 + y + i) * C + c0 + x];
    __syncthreads();
#pragma unroll
    for (int i = 0; i < 4; i++)
        out[(size_t)(c0 + y + i) * R + r0 + x] = t[x][y + i];
}

// ---------------- pipelined mma.sync tf32 GEMM ----------------
// D[m][n] = sum_k A[m][k] * Bt[n][k]   (Bt row-major [N][K])
// ALOAD 0: A = g_xn layout [b][k][s], m = b*4096+s  (k-major smem tile)
// ALOAD 1: A row-major [M][lda]                     ([m][k] smem tile)
// EPI 0: C[m][n];  EPI 1: out[b][n][s] + bias[n] + resid
#define STG    20480          // bytes per pipeline stage (A:10240 + B:10240)
#define GSMEM  (3 * STG)      // 61440
#define BOFF   10240

template<int ALOAD, int EPI, bool MG>
__global__ void __launch_bounds__(256)
gemm_mm(const float* __restrict__ A, const float* __restrict__ Bt,
        float* __restrict__ Cout, int M, int N, int K, int lda,
        const float* __restrict__ bias, const float* __restrict__ resid)
{
    extern __shared__ char smc[];
    uint32_t sb = smem_u32(smc);

    int tid = threadIdx.x, lane = tid & 31, w = tid >> 5;
    int wm = w & 3, wn = w >> 2;
    int m0 = blockIdx.y * 128;
    int n0 = blockIdx.x * 128;
    int mb = wm * 32, nb = wn * 64;
    int NT = K >> 4;

    const float* Ab0 = A;
    if (ALOAD == 0)
        Ab0 = A + (size_t)(m0 >> 12) * CHN * SP + (m0 & (SP - 1));

    float acc[2][8][4];
#pragma unroll
    for (int i = 0; i < 2; i++)
#pragma unroll
        for (int j = 0; j < 8; j++)
#pragma unroll
            for (int l = 0; l < 4; l++) acc[i][j][l] = 0.f;

    auto load_stage = [&](int slot, int k0) {
        uint32_t st = sb + slot * STG;
        if (ALOAD == 0) {
#pragma unroll
            for (int i = 0; i < 2; i++) {
                int cid = tid + i * 256;
                int kk = cid >> 5, mc = (cid & 31) * 4;
                cp16(st + kk * 544 + mc * 4,
                     Ab0 + (size_t)(k0 + kk) * SP + mc, true);
            }
        } else {
#pragma unroll
            for (int i = 0; i < 2; i++) {
                int cid = tid + i * 256;
                int row = cid >> 2, c = (cid & 3) * 4;
                bool v = !MG || (m0 + row) < M;
                cp16(st + row * 80 + c * 4,
                     A + (size_t)(m0 + row) * lda + k0 + c, v);
            }
        }
#pragma unroll
        for (int i = 0; i < 2; i++) {
            int cid = tid + i * 256;
            int row = cid >> 2, c = (cid & 3) * 4;
            cp16(st + BOFF + row * 80 + c * 4,
                 Bt + (size_t)(n0 + row) * K + k0 + c, true);
        }
    };

    load_stage(0, 0);  CP_COMMIT();
    load_stage(1, 16); CP_COMMIT();

    for (int t = 0; t < NT; t++) {
        if (t == NT - 1) CP_WAIT0(); else CP_WAIT1();
        __syncthreads();
        if (t + 2 < NT) { load_stage((t + 2) % 3, (t + 2) * 16); CP_COMMIT(); }

        int slot = t % 3;
        const float* As = (const float*)(smc + slot * STG);
        const float* Bs = (const float*)(smc + slot * STG + BOFF);
#pragma unroll
        for (int kc = 0; kc < 16; kc += 8) {
            int kr = kc + (lane & 3);
            unsigned a[2][4];
#pragma unroll
            for (int im = 0; im < 2; im++) {
                int mrow = mb + im * 16 + (lane >> 2);
                if (ALOAD == 0) {
                    a[im][0] = __float_as_uint(As[kr * 136 + mrow]);
                    a[im][1] = __float_as_uint(As[kr * 136 + mrow + 8]);
                    a[im][2] = __float_as_uint(As[(kr + 4) * 136 + mrow]);
                    a[im][3] = __float_as_uint(As[(kr + 4) * 136 + mrow + 8]);
                } else {
                    a[im][0] = __float_as_uint(As[mrow * 20 + kr]);
                    a[im][1] = __float_as_uint(As[(mrow + 8) * 20 + kr]);
                    a[im][2] = __float_as_uint(As[mrow * 20 + kr + 4]);
                    a[im][3] = __float_as_uint(As[(mrow + 8) * 20 + kr + 4]);
                }
            }
#pragma unroll
            for (int in_ = 0; in_ < 8; in_++) {
                int ncol = nb + in_ * 8 + (lane >> 2);
                unsigned b0 = __float_as_uint(Bs[ncol * 20 + kr]);
                unsigned b1 = __float_as_uint(Bs[ncol * 20 + kr + 4]);
#pragma unroll
                for (int im = 0; im < 2; im++)
                    mma_tf32(acc[im][in_], a[im][0], a[im][1], a[im][2],
                             a[im][3], b0, b1);
            }
        }
    }
    __syncthreads();

    // -------- epilogue (smem-staged, coalesced) --------
    float* Cs = (float*)smc;
    if (EPI == 0) {
#pragma unroll 1
        for (int ch = 0; ch < 4; ch++) {
            __syncthreads();
            if (wm == ch) {
#pragma unroll
                for (int im = 0; im < 2; im++) {
                    int r0 = im * 16 + (lane >> 2);
#pragma unroll
                    for (int in_ = 0; in_ < 8; in_++) {
                        int cc = nb + in_ * 8 + (lane & 3) * 2;
                        Cs[r0 * 132 + cc]           = acc[im][in_][0];
                        Cs[r0 * 132 + cc + 1]       = acc[im][in_][1];
                        Cs[(r0 + 8) * 132 + cc]     = acc[im][in_][2];
                        Cs[(r0 + 8) * 132 + cc + 1] = acc[im][in_][3];
                    }
                }
            }
            __syncthreads();
            for (int t = tid; t < 32 * 128; t += 256) {
                int ml = t >> 7, n = t & 127;
                int m = m0 + ch * 32 + ml;
                if (MG && m >= M) continue;
                Cout[(size_t)m * N + n0 + n] = Cs[ml * 132 + n];
            }
        }
    } else {
#pragma unroll 1
        for (int ch = 0; ch < 4; ch++) {
            __syncthreads();
            if (wn == (ch >> 1)) {
                int inlo = (ch & 1) * 4;
#pragma unroll
                for (int im = 0; im < 2; im++) {
                    int mrow = mb + im * 16 + (lane >> 2);
#pragma unroll
                    for (int ii = 0; ii < 4; ii++) {
                        int in_ = inlo + ii;
                        int nl = in_ * 8 + (lane & 3) * 2 - (ch & 1) * 32;
                        Cs[nl * 132 + mrow]           = acc[im][in_][0];
                        Cs[(nl + 1) * 132 + mrow]     = acc[im][in_][1];
                        Cs[nl * 132 + mrow + 8]       = acc[im][in_][2];
                        Cs[(nl + 1) * 132 + mrow + 8] = acc[im][in_][3];
                    }
                }
            }
            __syncthreads();
            for (int t = tid; t < 32 * 128; t += 256) {
                int nl = t >> 7, ml = t & 127;
                int n = n0 + ch * 32 + nl;
                int m = m0 + ml;
                int b = m >> 12, s = m & (SP - 1);
                size_t addr = (size_t)b * CHN * SP + (size_t)n * SP + s;
                Cout[addr] = Cs[nl * 132 + ml] + bias[n] + resid[addr];
            }
        }
    }
}

// ---------------- attention: 4 rows per warp iteration ----------------
#define ASMEM ((80 * 80 + 77 * 80 + 32 * 80) * 4)
__global__ void __launch_bounds__(256) attn_kernel()
{
    extern __shared__ float sm[];
    float* k_s = sm;                   // [80 d][80 t-pad]
    float* v_s = sm + 80 * 80;         // [77 t][80 d]  (also K staging)
    float* p_s = v_s + 77 * 80;        // [32 rows][80]

    int tid = threadIdx.x, lane = tid & 31, w = tid >> 5;
    int b = blockIdx.z, h = blockIdx.y;
    int s0 = blockIdx.x * 256;

    const float* kb = g_k + (size_t)b * TT * INNER + h * HDIM;
    const float* vb = g_v + (size_t)b * TT * INNER + h * HDIM;

    for (int i = tid; i < TT * HDIM; i += 256) {
        int t = i / HDIM, d = i - t * HDIM;
        v_s[t * 80 + d] = kb[(size_t)t * INNER + d];
    }
    __syncthreads();
    for (int i = tid; i < TT * HDIM; i += 256) {
        int t = i / HDIM, d = i - t * HDIM;
        k_s[d * 80 + t] = v_s[t * 80 + d];
    }
    __syncthreads();
    for (int i = tid; i < TT * HDIM; i += 256) {
        int t = i / HDIM, d = i - t * HDIM;
        v_s[t * 80 + d] = vb[(size_t)t * INNER + d];
    }
    __syncthreads();

    const float scale = 0.11180339887498949f;

    for (int it = 0; it < 8; it++) {
        int srow = s0 + w * 32 + it * 4;
        const float* qp = g_q + ((size_t)b * SP + srow) * INNER + h * HDIM;

        float sc0[4] = {0, 0, 0, 0}, sc1[4] = {0, 0, 0, 0}, sc2[4] = {0, 0, 0, 0};
#pragma unroll 4
        for (int d4 = 0; d4 < HDIM / 4; d4++) {
            float4 qv[4];
#pragma unroll
            for (int r = 0; r < 4; r++)
                qv[r] = *(const float4*)(qp + (size_t)r * INNER + d4 * 4);
#pragma unroll
            for (int j = 0; j < 4; j++) {
                int d = d4 * 4 + j;
                float2 k01 = *(const float2*)&k_s[d * 80 + 2 * lane];
                float kx = k_s[d * 80 + 64 + lane];
#pragma unroll
                for (int r = 0; r < 4; r++) {
                    float q = (&qv[r].x)[j];
                    sc0[r] = fmaf(q, k01.x, sc0[r]);
                    sc1[r] = fmaf(q, k01.y, sc1[r]);
                    sc2[r] = fmaf(q, kx,    sc2[r]);
                }
            }
        }
#pragma unroll
        for (int r = 0; r < 4; r++) {
            float a0 = sc0[r] * scale, a1 = sc1[r] * scale;
            float a2 = (lane < TT - 64) ? sc2[r] * scale : -1e30f;
            float mx = fmaxf(a0, fmaxf(a1, a2));
#pragma unroll
            for (int off = 16; off; off >>= 1)
                mx = fmaxf(mx, __shfl_xor_sync(0xffffffffu, mx, off));
            float e0 = __expf(a0 - mx), e1 = __expf(a1 - mx);
            float e2 = (lane < TT - 64) ? __expf(a2 - mx) : 0.f;
            float sum = e0 + e1 + e2;
#pragma unroll
            for (int off = 16; off; off >>= 1)
                sum += __shfl_xor_sync(0xffffffffu, sum, off);
            float inv = 1.f / sum;
            float* pr = p_s + (w * 4 + r) * 80;
            *(float2*)&pr[2 * lane] = make_float2(e0 * inv, e1 * inv);
            if (lane < TT - 64) pr[64 + lane] = e2 * inv;
        }
        __syncwarp();

        float o0[4] = {0, 0, 0, 0}, o1[4] = {0, 0, 0, 0}, o2[4] = {0, 0, 0, 0};
#pragma unroll 7
        for (int t = 0; t < TT; t++) {
            float2 v01 = *(const float2*)&v_s[t * 80 + 2 * lane];
            float vx = v_s[t * 80 + 64 + lane];
#pragma unroll
            for (int r = 0; r < 4; r++) {
                float p = p_s[(w * 4 + r) * 80 + t];
                o0[r] = fmaf(p, v01.x, o0[r]);
                o1[r] = fmaf(p, v01.y, o1[r]);
                o2[r] = fmaf(p, vx,    o2[r]);
            }
        }
#pragma unroll
        for (int r = 0; r < 4; r++) {
            float* op = g_at + ((size_t)b * SP + srow + r) * INNER + h * HDIM;
            *(float2*)&op[2 * lane] = make_float2(o0[r], o1[r]);
            if (lane < HDIM - 64) op[64 + lane] = o2[r];
        }
        __syncwarp();
    }
}

// ---------------- launch ----------------
extern "C" void kernel_launch(void* const* d_in, const int* in_sizes, int n_in,
                              void* d_out, int out_size)
{
    (void)in_sizes; (void)n_in; (void)out_size;
    const float* hs  = (const float*)d_in[0];
    const float* enc = (const float*)d_in[1];
    const float* lnw = (const float*)d_in[2];
    const float* lnb = (const float*)d_in[3];
    const float* wq  = (const float*)d_in[4];
    const float* wk  = (const float*)d_in[5];
    const float* wv  = (const float*)d_in[6];
    const float* wo  = (const float*)d_in[7];
    const float* bo  = (const float*)d_in[8];
    float* out = (float*)d_out;

    float *p_xn, *p_q, *p_k, *p_v, *p_at, *p_wqt, *p_wkt, *p_wvt, *p_wot;
    cudaGetSymbolAddress((void**)&p_xn,  g_xn);
    cudaGetSymbolAddress((void**)&p_q,   g_q);
    cudaGetSymbolAddress((void**)&p_k,   g_k);
    cudaGetSymbolAddress((void**)&p_v,   g_v);
    cudaGetSymbolAddress((void**)&p_at,  g_at);
    cudaGetSymbolAddress((void**)&p_wqt, g_wqt);
    cudaGetSymbolAddress((void**)&p_wkt, g_wkt);
    cudaGetSymbolAddress((void**)&p_wvt, g_wvt);
    cudaGetSymbolAddress((void**)&p_wot, g_wot);

    cudaFuncSetAttribute(gemm_mm<0, 0, false>,
                         cudaFuncAttributeMaxDynamicSharedMemorySize, GSMEM);
    cudaFuncSetAttribute(gemm_mm<1, 0, true>,
                         cudaFuncAttributeMaxDynamicSharedMemorySize, GSMEM);
    cudaFuncSetAttribute(gemm_mm<1, 1, false>,
                         cudaFuncAttributeMaxDynamicSharedMemorySize, GSMEM);
    cudaFuncSetAttribute(attn_kernel,
                         cudaFuncAttributeMaxDynamicSharedMemorySize, ASMEM);

    // weight transposes: Wt[n][k] = W[k][n]
    transpose_k<<<dim3(INNER / 32, CHN / 32), 256>>>(wq, p_wqt, CHN, INNER);
    transpose_k<<<dim3(INNER / 32, XDIM / 32), 256>>>(wk, p_wkt, XDIM, INNER);
    transpose_k<<<dim3(INNER / 32, XDIM / 32), 256>>>(wv, p_wvt, XDIM, INNER);
    transpose_k<<<dim3(CHN / 32, INNER / 32), 256>>>(wo, p_wot, INNER, CHN);

    ln_kernel<<<dim3(SP / 256, BATCH), 256>>>(hs, lnw, lnb);

    // Q = xn @ wq
    gemm_mm<0, 0, false><<<dim3(INNER / 128, (BATCH * SP) / 128), 256, GSMEM>>>(
        p_xn, p_wqt, p_q, BATCH * SP, INNER, CHN, 0, nullptr, nullptr);

    // K, V = enc @ wk / wv   (M = 1232, guarded)
    int mkv = (BATCH * TT + 127) / 128;
    gemm_mm<1, 0, true><<<dim3(INNER / 128, mkv), 256, GSMEM>>>(
        enc, p_wkt, p_k, BATCH * TT, INNER, XDIM, XDIM, nullptr, nullptr);
    gemm_mm<1, 0, true><<<dim3(INNER / 128, mkv), 256, GSMEM>>>(
        enc, p_wvt, p_v, BATCH * TT, INNER, XDIM, XDIM, nullptr, nullptr);

    attn_kernel<<<dim3(SP / 256, NHE, BATCH), 256, ASMEM>>>();

    // out = at @ wo + bo + residual (transposed store)
    gemm_mm<1, 1, false><<<dim3(CHN / 128, (BATCH * SP) / 128), 256, GSMEM>>>(
        p_at, p_wot, out, BATCH * SP, CHN, INNER, INNER, bo, hs);
}

// round 4
// speedup vs baseline: 1.5368x; 1.4351x over previous
#include <cuda_runtime.h>
#include <cuda_bf16.h>
#include <math.h>
#include <stdint.h>

#define BATCH 16
#define CHN   640
#define SP    4096
#define TT    77
#define XDIM  768
#define NHE   8
#define HDIM  80
#define INNER 640

// ---------------- scratch ----------------
__device__ float g_xn [(size_t)BATCH * CHN * SP];
__device__ float g_q  [(size_t)BATCH * SP * INNER];
__device__ float g_k  [(size_t)BATCH * TT * INNER];
__device__ float g_v  [(size_t)BATCH * TT * INNER];
__device__ float g_at [(size_t)BATCH * SP * INNER];
__device__ float g_wqt[(size_t)INNER * CHN];
__device__ float g_wkt[(size_t)INNER * XDIM];
__device__ float g_wvt[(size_t)INNER * XDIM];
__device__ float g_wot[(size_t)CHN * INNER];

// ---------------- helpers ----------------
__device__ __forceinline__ uint32_t smem_u32(const void* p) {
    uint32_t a;
    asm("{ .reg .u64 t; cvta.to.shared.u64 t, %1; cvt.u32.u64 %0, t; }"
        : "=r"(a) : "l"(p));
    return a;
}
__device__ __forceinline__ void cp16(uint32_t dst, const float* src, bool v) {
    int sz = v ? 16 : 0;
    asm volatile("cp.async.cg.shared.global [%0], [%1], 16, %2;"
                 :: "r"(dst), "l"(src), "r"(sz) : "memory");
}
#define CP_COMMIT() asm volatile("cp.async.commit_group;" ::: "memory")
#define CP_WAIT1()  asm volatile("cp.async.wait_group 1;" ::: "memory")
#define CP_WAIT0()  asm volatile("cp.async.wait_group 0;" ::: "memory")

__device__ __forceinline__ void mma_tf32(float c[4], unsigned a0, unsigned a1,
                                         unsigned a2, unsigned a3,
                                         unsigned b0, unsigned b1)
{
    asm volatile(
        "mma.sync.aligned.m16n8k8.row.col.f32.tf32.tf32.f32 "
        "{%0,%1,%2,%3},{%4,%5,%6,%7},{%8,%9},{%0,%1,%2,%3};"
        : "+f"(c[0]), "+f"(c[1]), "+f"(c[2]), "+f"(c[3])
        : "r"(a0), "r"(a1), "r"(a2), "r"(a3), "r"(b0), "r"(b1));
}

// ---------------- LayerNorm ----------------
__global__ void __launch_bounds__(256) ln_kernel(const float* __restrict__ x,
                                                 const float* __restrict__ w,
                                                 const float* __restrict__ bia)
{
    int s = blockIdx.x * 256 + threadIdx.x;
    int b = blockIdx.y;
    const float* xp = x + (size_t)b * CHN * SP + s;
    float sum = 0.f, sumsq = 0.f;
    for (int c = 0; c < CHN; c++) { float v = xp[(size_t)c * SP]; sum += v; sumsq += v * v; }
    float mu = sum * (1.0f / CHN);
    float var = sumsq * (1.0f / CHN) - mu * mu;
    float rstd = rsqrtf(var + 1e-6f);
    float* op = g_xn + (size_t)b * CHN * SP + s;
    for (int c = 0; c < CHN; c++) {
        float v = xp[(size_t)c * SP];
        op[(size_t)c * SP] = (v - mu) * rstd * w[c] + bia[c];
    }
}

// ---------------- weight transpose [R][C] -> [C][R] ----------------
__global__ void __launch_bounds__(256) transpose_k(const float* __restrict__ in,
                                                   float* __restrict__ out, int R, int C)
{
    __shared__ float t[32][33];
    int c0 = blockIdx.x * 32, r0 = blockIdx.y * 32;
    int x = threadIdx.x & 31, y = (threadIdx.x >> 5) * 4;
#pragma unroll
    for (int i = 0; i < 4; i++)
        t[y + i][x] = in[(size_t)(r0 + y + i) * C + c0 + x];
    __syncthreads();
#pragma unroll
    for (int i = 0; i < 4; i++)
        out[(size_t)(c0 + y + i) * R + r0 + x] = t[x][y + i];
}

// ---------------- pipelined mma.sync tf32 GEMM, BK=32 ----------------
// D[m][n] = sum_k A[m][k] * Bt[n][k]   (Bt row-major [N][K])
// ALOAD 0: A = g_xn layout [b][k][s], m = b*4096+s  (smem [k][m] pitch 136)
// ALOAD 1: A row-major [M][lda]                     (smem [m][k] pitch 36)
// EPI 0: C[m][n];  EPI 1: out[b][n][s] + bias[n] + resid
#define BOFFS  18432
#define STG    36864
#define GSMEM  (3 * STG)      // 110592

template<int ALOAD, int EPI, bool MG>
__global__ void __launch_bounds__(256, 2)
gemm_mm(const float* __restrict__ A, const float* __restrict__ Bt,
        float* __restrict__ Cout, int M, int N, int K, int lda,
        const float* __restrict__ bias, const float* __restrict__ resid)
{
    extern __shared__ char smc[];
    uint32_t sb = smem_u32(smc);

    int tid = threadIdx.x, lane = tid & 31, w = tid >> 5;
    int wm = w & 3, wn = w >> 2;
    int m0 = blockIdx.y * 128;
    int n0 = blockIdx.x * 128;
    int mb = wm * 32, nb = wn * 64;
    int NT = K >> 5;

    const float* Ab0 = A;
    if (ALOAD == 0)
        Ab0 = A + (size_t)(m0 >> 12) * CHN * SP + (m0 & (SP - 1));

    float acc[2][8][4];
#pragma unroll
    for (int i = 0; i < 2; i++)
#pragma unroll
        for (int j = 0; j < 8; j++)
#pragma unroll
            for (int l = 0; l < 4; l++) acc[i][j][l] = 0.f;

    auto load_stage = [&](int slot, int k0) {
        uint32_t st = sb + slot * STG;
        if (ALOAD == 0) {
#pragma unroll
            for (int i = 0; i < 4; i++) {
                int cid = tid + i * 256;
                int kk = cid >> 5, mc = (cid & 31) * 4;
                cp16(st + kk * 544 + mc * 4,
                     Ab0 + (size_t)(k0 + kk) * SP + mc, true);
            }
        } else {
#pragma unroll
            for (int i = 0; i < 4; i++) {
                int cid = tid + i * 256;
                int row = cid >> 3, ch = cid & 7;
                bool v = !MG || (m0 + row) < M;
                cp16(st + row * 144 + ch * 16,
                     A + (size_t)(m0 + row) * lda + k0 + ch * 4, v);
            }
        }
#pragma unroll
        for (int i = 0; i < 4; i++) {
            int cid = tid + i * 256;
            int row = cid >> 3, ch = cid & 7;
            cp16(st + BOFFS + row * 144 + ch * 16,
                 Bt + (size_t)(n0 + row) * K + k0 + ch * 4, true);
        }
    };

    auto lda_frag = [&](unsigned af[2][4], const float* As, int kc) {
        int kr = kc + (lane & 3);
#pragma unroll
        for (int im = 0; im < 2; im++) {
            int mrow = mb + im * 16 + (lane >> 2);
            if (ALOAD == 0) {
                af[im][0] = __float_as_uint(As[kr * 136 + mrow]);
                af[im][1] = __float_as_uint(As[kr * 136 + mrow + 8]);
                af[im][2] = __float_as_uint(As[(kr + 4) * 136 + mrow]);
                af[im][3] = __float_as_uint(As[(kr + 4) * 136 + mrow + 8]);
            } else {
                af[im][0] = __float_as_uint(As[mrow * 36 + kr]);
                af[im][1] = __float_as_uint(As[(mrow + 8) * 36 + kr]);
                af[im][2] = __float_as_uint(As[mrow * 36 + kr + 4]);
                af[im][3] = __float_as_uint(As[(mrow + 8) * 36 + kr + 4]);
            }
        }
    };

    load_stage(0, 0);  CP_COMMIT();
    load_stage(1, 32); CP_COMMIT();

    for (int t = 0; t < NT; t++) {
        if (t == NT - 1) CP_WAIT0(); else CP_WAIT1();
        __syncthreads();
        if (t + 2 < NT) { load_stage((t + 2) % 3, (t + 2) * 32); CP_COMMIT(); }

        int slot = t % 3;
        const float* As = (const float*)(smc + slot * STG);
        const float* Bs = (const float*)(smc + slot * STG + BOFFS);

        unsigned ac[2][4], an[2][4];
        lda_frag(ac, As, 0);
#pragma unroll
        for (int kc = 0; kc < 4; kc++) {
            if (kc < 3) lda_frag(an, As, (kc + 1) * 8);
            int kr = kc * 8 + (lane & 3);
#pragma unroll
            for (int half = 0; half < 2; half++) {
                unsigned bb[4][2];
#pragma unroll
                for (int i = 0; i < 4; i++) {
                    int ncol = nb + (half * 4 + i) * 8 + (lane >> 2);
                    bb[i][0] = __float_as_uint(Bs[ncol * 36 + kr]);
                    bb[i][1] = __float_as_uint(Bs[ncol * 36 + kr + 4]);
                }
#pragma unroll
                for (int i = 0; i < 4; i++) {
                    int in_ = half * 4 + i;
#pragma unroll
                    for (int im = 0; im < 2; im++)
                        mma_tf32(acc[im][in_], ac[im][0], ac[im][1], ac[im][2],
                                 ac[im][3], bb[i][0], bb[i][1]);
                }
            }
            if (kc < 3) {
#pragma unroll
                for (int im = 0; im < 2; im++)
#pragma unroll
                    for (int j = 0; j < 4; j++) ac[im][j] = an[im][j];
            }
        }
    }
    __syncthreads();

    // -------- epilogue (smem-staged, coalesced) --------
    float* Cs = (float*)smc;
    if (EPI == 0) {
#pragma unroll 1
        for (int ch = 0; ch < 4; ch++) {
            __syncthreads();
            if (wm == ch) {
#pragma unroll
                for (int im = 0; im < 2; im++) {
                    int r0 = im * 16 + (lane >> 2);
#pragma unroll
                    for (int in_ = 0; in_ < 8; in_++) {
                        int cc = nb + in_ * 8 + (lane & 3) * 2;
                        Cs[r0 * 132 + cc]           = acc[im][in_][0];
                        Cs[r0 * 132 + cc + 1]       = acc[im][in_][1];
                        Cs[(r0 + 8) * 132 + cc]     = acc[im][in_][2];
                        Cs[(r0 + 8) * 132 + cc + 1] = acc[im][in_][3];
                    }
                }
            }
            __syncthreads();
            for (int t = tid; t < 32 * 128; t += 256) {
                int ml = t >> 7, n = t & 127;
                int m = m0 + ch * 32 + ml;
                if (MG && m >= M) continue;
                Cout[(size_t)m * N + n0 + n] = Cs[ml * 132 + n];
            }
        }
    } else {
#pragma unroll 1
        for (int ch = 0; ch < 4; ch++) {
            __syncthreads();
            if (wn == (ch >> 1)) {
                int inlo = (ch & 1) * 4;
#pragma unroll
                for (int im = 0; im < 2; im++) {
                    int mrow = mb + im * 16 + (lane >> 2);
#pragma unroll
                    for (int ii = 0; ii < 4; ii++) {
                        int in_ = inlo + ii;
                        int nl = in_ * 8 + (lane & 3) * 2 - (ch & 1) * 32;
                        Cs[nl * 132 + mrow]           = acc[im][in_][0];
                        Cs[(nl + 1) * 132 + mrow]     = acc[im][in_][1];
                        Cs[nl * 132 + mrow + 8]       = acc[im][in_][2];
                        Cs[(nl + 1) * 132 + mrow + 8] = acc[im][in_][3];
                    }
                }
            }
            __syncthreads();
            for (int t = tid; t < 32 * 128; t += 256) {
                int nl = t >> 7, ml = t & 127;
                int n = n0 + ch * 32 + nl;
                int m = m0 + ml;
                int b = m >> 12, s = m & (SP - 1);
                size_t addr = (size_t)b * CHN * SP + (size_t)n * SP + s;
                Cout[addr] = Cs[nl * 132 + ml] + bias[n] + resid[addr];
            }
        }
    }
}

// ---------------- attention: 4 rows per warp iteration ----------------
#define ASMEM ((80 * 80 + 77 * 80 + 32 * 80) * 4)
__global__ void __launch_bounds__(256) attn_kernel()
{
    extern __shared__ float sm[];
    float* k_s = sm;                   // [80 d][80 t-pad]
    float* v_s = sm + 80 * 80;         // [77 t][80 d]  (also K staging)
    float* p_s = v_s + 77 * 80;        // [32 rows][80]

    int tid = threadIdx.x, lane = tid & 31, w = tid >> 5;
    int b = blockIdx.z, h = blockIdx.y;
    int s0 = blockIdx.x * 256;

    const float* kb = g_k + (size_t)b * TT * INNER + h * HDIM;
    const float* vb = g_v + (size_t)b * TT * INNER + h * HDIM;

    for (int i = tid; i < TT * HDIM; i += 256) {
        int t = i / HDIM, d = i - t * HDIM;
        v_s[t * 80 + d] = kb[(size_t)t * INNER + d];
    }
    __syncthreads();
    for (int i = tid; i < TT * HDIM; i += 256) {
        int t = i / HDIM, d = i - t * HDIM;
        k_s[d * 80 + t] = v_s[t * 80 + d];
    }
    __syncthreads();
    for (int i = tid; i < TT * HDIM; i += 256) {
        int t = i / HDIM, d = i - t * HDIM;
        v_s[t * 80 + d] = vb[(size_t)t * INNER + d];
    }
    __syncthreads();

    const float scale = 0.11180339887498949f;

    for (int it = 0; it < 8; it++) {
        int srow = s0 + w * 32 + it * 4;
        const float* qp = g_q + ((size_t)b * SP + srow) * INNER + h * HDIM;

        float sc0[4] = {0, 0, 0, 0}, sc1[4] = {0, 0, 0, 0}, sc2[4] = {0, 0, 0, 0};
#pragma unroll 4
        for (int d4 = 0; d4 < HDIM / 4; d4++) {
            float4 qv[4];
#pragma unroll
            for (int r = 0; r < 4; r++)
                qv[r] = *(const float4*)(qp + (size_t)r * INNER + d4 * 4);
#pragma unroll
            for (int j = 0; j < 4; j++) {
                int d = d4 * 4 + j;
                float2 k01 = *(const float2*)&k_s[d * 80 + 2 * lane];
                float kx = k_s[d * 80 + 64 + lane];
#pragma unroll
                for (int r = 0; r < 4; r++) {
                    float q = (&qv[r].x)[j];
                    sc0[r] = fmaf(q, k01.x, sc0[r]);
                    sc1[r] = fmaf(q, k01.y, sc1[r]);
                    sc2[r] = fmaf(q, kx,    sc2[r]);
                }
            }
        }
#pragma unroll
        for (int r = 0; r < 4; r++) {
            float a0 = sc0[r] * scale, a1 = sc1[r] * scale;
            float a2 = (lane < TT - 64) ? sc2[r] * scale : -1e30f;
            float mx = fmaxf(a0, fmaxf(a1, a2));
#pragma unroll
            for (int off = 16; off; off >>= 1)
                mx = fmaxf(mx, __shfl_xor_sync(0xffffffffu, mx, off));
            float e0 = __expf(a0 - mx), e1 = __expf(a1 - mx);
            float e2 = (lane < TT - 64) ? __expf(a2 - mx) : 0.f;
            float sum = e0 + e1 + e2;
#pragma unroll
            for (int off = 16; off; off >>= 1)
                sum += __shfl_xor_sync(0xffffffffu, sum, off);
            float inv = 1.f / sum;
            float* pr = p_s + (w * 4 + r) * 80;
            *(float2*)&pr[2 * lane] = make_float2(e0 * inv, e1 * inv);
            if (lane < TT - 64) pr[64 + lane] = e2 * inv;
        }
        __syncwarp();

        float o0[4] = {0, 0, 0, 0}, o1[4] = {0, 0, 0, 0}, o2[4] = {0, 0, 0, 0};
#pragma unroll 7
        for (int t = 0; t < TT; t++) {
            float2 v01 = *(const float2*)&v_s[t * 80 + 2 * lane];
            float vx = v_s[t * 80 + 64 + lane];
#pragma unroll
            for (int r = 0; r < 4; r++) {
                float p = p_s[(w * 4 + r) * 80 + t];
                o0[r] = fmaf(p, v01.x, o0[r]);
                o1[r] = fmaf(p, v01.y, o1[r]);
                o2[r] = fmaf(p, vx,    o2[r]);
            }
        }
#pragma unroll
        for (int r = 0; r < 4; r++) {
            float* op = g_at + ((size_t)b * SP + srow + r) * INNER + h * HDIM;
            *(float2*)&op[2 * lane] = make_float2(o0[r], o1[r]);
            if (lane < HDIM - 64) op[64 + lane] = o2[r];
        }
        __syncwarp();
    }
}

// ---------------- launch ----------------
extern "C" void kernel_launch(void* const* d_in, const int* in_sizes, int n_in,
                              void* d_out, int out_size)
{
    (void)in_sizes; (void)n_in; (void)out_size;
    const float* hs  = (const float*)d_in[0];
    const float* enc = (const float*)d_in[1];
    const float* lnw = (const float*)d_in[2];
    const float* lnb = (const float*)d_in[3];
    const float* wq  = (const float*)d_in[4];
    const float* wk  = (const float*)d_in[5];
    const float* wv  = (const float*)d_in[6];
    const float* wo  = (const float*)d_in[7];
    const float* bo  = (const float*)d_in[8];
    float* out = (float*)d_out;

    float *p_xn, *p_q, *p_k, *p_v, *p_at, *p_wqt, *p_wkt, *p_wvt, *p_wot;
    cudaGetSymbolAddress((void**)&p_xn,  g_xn);
    cudaGetSymbolAddress((void**)&p_q,   g_q);
    cudaGetSymbolAddress((void**)&p_k,   g_k);
    cudaGetSymbolAddress((void**)&p_v,   g_v);
    cudaGetSymbolAddress((void**)&p_at,  g_at);
    cudaGetSymbolAddress((void**)&p_wqt, g_wqt);
    cudaGetSymbolAddress((void**)&p_wkt, g_wkt);
    cudaGetSymbolAddress((void**)&p_wvt, g_wvt);
    cudaGetSymbolAddress((void**)&p_wot, g_wot);

    cudaFuncSetAttribute(gemm_mm<0, 0, false>,
                         cudaFuncAttributeMaxDynamicSharedMemorySize, GSMEM);
    cudaFuncSetAttribute(gemm_mm<1, 0, true>,
                         cudaFuncAttributeMaxDynamicSharedMemorySize, GSMEM);
    cudaFuncSetAttribute(gemm_mm<1, 1, false>,
                         cudaFuncAttributeMaxDynamicSharedMemorySize, GSMEM);
    cudaFuncSetAttribute(attn_kernel,
                         cudaFuncAttributeMaxDynamicSharedMemorySize, ASMEM);

    // weight transposes: Wt[n][k] = W[k][n]
    transpose_k<<<dim3(INNER / 32, CHN / 32), 256>>>(wq, p_wqt, CHN, INNER);
    transpose_k<<<dim3(INNER / 32, XDIM / 32), 256>>>(wk, p_wkt, XDIM, INNER);
    transpose_k<<<dim3(INNER / 32, XDIM / 32), 256>>>(wv, p_wvt, XDIM, INNER);
    transpose_k<<<dim3(CHN / 32, INNER / 32), 256>>>(wo, p_wot, INNER, CHN);

    ln_kernel<<<dim3(SP / 256, BATCH), 256>>>(hs, lnw, lnb);

    // Q = xn @ wq
    gemm_mm<0, 0, false><<<dim3(INNER / 128, (BATCH * SP) / 128), 256, GSMEM>>>(
        p_xn, p_wqt, p_q, BATCH * SP, INNER, CHN, 0, nullptr, nullptr);

    // K, V = enc @ wk / wv   (M = 1232, guarded)
    int mkv = (BATCH * TT + 127) / 128;
    gemm_mm<1, 0, true><<<dim3(INNER / 128, mkv), 256, GSMEM>>>(
        enc, p_wkt, p_k, BATCH * TT, INNER, XDIM, XDIM, nullptr, nullptr);
    gemm_mm<1, 0, true><<<dim3(INNER / 128, mkv), 256, GSMEM>>>(
        enc, p_wvt, p_v, BATCH * TT, INNER, XDIM, XDIM, nullptr, nullptr);

    attn_kernel<<<dim3(SP / 256, NHE, BATCH), 256, ASMEM>>>();

    // out = at @ wo + bo + residual (transposed store)
    gemm_mm<1, 1, false><<<dim3(CHN / 128, (BATCH * SP) / 128), 256, GSMEM>>>(
        p_at, p_wot, out, BATCH * SP, CHN, INNER, INNER, bo, hs);
}

// round 5
// speedup vs baseline: 2.1279x; 1.3847x over previous
#include <cuda_runtime.h>
#include <cuda_bf16.h>
#include <math.h>
#include <stdint.h>

#define BATCH 16
#define CHN   640
#define SP    4096
#define TT    77
#define XDIM  768
#define NHE   8
#define HDIM  80
#define INNER 640

// ---------------- scratch ----------------
__device__ float g_xn [(size_t)BATCH * CHN * SP];
__device__ float g_q  [(size_t)BATCH * SP * INNER];
__device__ float g_k  [(size_t)BATCH * TT * INNER];
__device__ float g_v  [(size_t)BATCH * TT * INNER];
__device__ float g_at [(size_t)BATCH * SP * INNER];

// ---------------- helpers ----------------
__device__ __forceinline__ uint32_t smem_u32(const void* p) {
    uint32_t a;
    asm("{ .reg .u64 t; cvta.to.shared.u64 t, %1; cvt.u32.u64 %0, t; }"
        : "=r"(a) : "l"(p));
    return a;
}
__device__ __forceinline__ void cp16(uint32_t dst, const float* src, bool v) {
    int sz = v ? 16 : 0;
    asm volatile("cp.async.cg.shared.global [%0], [%1], 16, %2;"
                 :: "r"(dst), "l"(src), "r"(sz) : "memory");
}
#define CP_COMMIT() asm volatile("cp.async.commit_group;" ::: "memory")
#define CP_WAIT1()  asm volatile("cp.async.wait_group 1;" ::: "memory")
#define CP_WAIT0()  asm volatile("cp.async.wait_group 0;" ::: "memory")

__device__ __forceinline__ void mma_tf32(float c[4], unsigned a0, unsigned a1,
                                         unsigned a2, unsigned a3,
                                         unsigned b0, unsigned b1)
{
    asm volatile(
        "mma.sync.aligned.m16n8k8.row.col.f32.tf32.tf32.f32 "
        "{%0,%1,%2,%3},{%4,%5,%6,%7},{%8,%9},{%0,%1,%2,%3};"
        : "+f"(c[0]), "+f"(c[1]), "+f"(c[2]), "+f"(c[3])
        : "r"(a0), "r"(a1), "r"(a2), "r"(a3), "r"(b0), "r"(b1));
}

// ---------------- LayerNorm ----------------
__global__ void __launch_bounds__(256) ln_kernel(const float* __restrict__ x,
                                                 const float* __restrict__ w,
                                                 const float* __restrict__ bia)
{
    int s = blockIdx.x * 256 + threadIdx.x;
    int b = blockIdx.y;
    const float* xp = x + (size_t)b * CHN * SP + s;
    float sum = 0.f, sumsq = 0.f;
    for (int c = 0; c < CHN; c++) { float v = xp[(size_t)c * SP]; sum += v; sumsq += v * v; }
    float mu = sum * (1.0f / CHN);
    float var = sumsq * (1.0f / CHN) - mu * mu;
    float rstd = rsqrtf(var + 1e-6f);
    float* op = g_xn + (size_t)b * CHN * SP + s;
    for (int c = 0; c < CHN; c++) {
        float v = xp[(size_t)c * SP];
        op[(size_t)c * SP] = (v - mu) * rstd * w[c] + bia[c];
    }
}

// ---------------- pipelined mma.sync tf32 GEMM, BK=32 ----------------
// D[m][n] = sum_k A[m][k] * Bw[k][n]   (Bw row-major [K][N], loaded directly)
// ALOAD 0: A = g_xn layout [b][k][s], m = b*4096+s  (smem [k][m] pitch 136)
// ALOAD 1: A row-major [M][lda]                     (smem [m][k] pitch 36)
// EPI 0: C[m][n];  EPI 1: out[b][n][s] + bias[n] + resid
#define BOFFS  18432
#define STG    35840          // A(<=18432) + B(32*544=17408)
#define GSMEM  (3 * STG)      // 107520

template<int ALOAD, int EPI, bool MG>
__global__ void __launch_bounds__(256, 2)
gemm_mm(const float* __restrict__ A, const float* __restrict__ Bw,
        float* __restrict__ Cout, int M, int N, int K, int lda,
        const float* __restrict__ bias, const float* __restrict__ resid)
{
    extern __shared__ char smc[];
    uint32_t sb = smem_u32(smc);

    int tid = threadIdx.x, lane = tid & 31, w = tid >> 5;
    int wm = w & 3, wn = w >> 2;
    int m0 = blockIdx.y * 128;
    int n0 = blockIdx.x * 128;
    int mb = wm * 32, nb = wn * 64;
    int NT = K >> 5;

    const float* Ab0 = A;
    if (ALOAD == 0)
        Ab0 = A + (size_t)(m0 >> 12) * CHN * SP + (m0 & (SP - 1));

    float acc[2][8][4];
#pragma unroll
    for (int i = 0; i < 2; i++)
#pragma unroll
        for (int j = 0; j < 8; j++)
#pragma unroll
            for (int l = 0; l < 4; l++) acc[i][j][l] = 0.f;

    auto load_stage = [&](int slot, int k0) {
        uint32_t st = sb + slot * STG;
        if (ALOAD == 0) {
#pragma unroll
            for (int i = 0; i < 4; i++) {
                int cid = tid + i * 256;
                int kk = cid >> 5, mc = (cid & 31) * 4;
                cp16(st + kk * 544 + mc * 4,
                     Ab0 + (size_t)(k0 + kk) * SP + mc, true);
            }
        } else {
#pragma unroll
            for (int i = 0; i < 4; i++) {
                int cid = tid + i * 256;
                int row = cid >> 3, ch = cid & 7;
                bool v = !MG || (m0 + row) < M;
                cp16(st + row * 144 + ch * 16,
                     A + (size_t)(m0 + row) * lda + k0 + ch * 4, v);
            }
        }
        // B direct: [k][n] tile, pitch 136 floats (544B)
#pragma unroll
        for (int i = 0; i < 4; i++) {
            int cid = tid + i * 256;
            int row = cid >> 5, ch = cid & 31;
            cp16(st + BOFFS + row * 544 + ch * 16,
                 Bw + (size_t)(k0 + row) * N + n0 + ch * 4, true);
        }
    };

    auto lda_frag = [&](unsigned af[2][4], const float* As, int kc) {
        int kr = kc + (lane & 3);
#pragma unroll
        for (int im = 0; im < 2; im++) {
            int mrow = mb + im * 16 + (lane >> 2);
            if (ALOAD == 0) {
                af[im][0] = __float_as_uint(As[kr * 136 + mrow]);
                af[im][1] = __float_as_uint(As[kr * 136 + mrow + 8]);
                af[im][2] = __float_as_uint(As[(kr + 4) * 136 + mrow]);
                af[im][3] = __float_as_uint(As[(kr + 4) * 136 + mrow + 8]);
            } else {
                af[im][0] = __float_as_uint(As[mrow * 36 + kr]);
                af[im][1] = __float_as_uint(As[(mrow + 8) * 36 + kr]);
                af[im][2] = __float_as_uint(As[mrow * 36 + kr + 4]);
                af[im][3] = __float_as_uint(As[(mrow + 8) * 36 + kr + 4]);
            }
        }
    };

    load_stage(0, 0);  CP_COMMIT();
    load_stage(1, 32); CP_COMMIT();

    for (int t = 0; t < NT; t++) {
        if (t == NT - 1) CP_WAIT0(); else CP_WAIT1();
        __syncthreads();
        if (t + 2 < NT) { load_stage((t + 2) % 3, (t + 2) * 32); CP_COMMIT(); }

        int slot = t % 3;
        const float* As = (const float*)(smc + slot * STG);
        const float* Bs = (const float*)(smc + slot * STG + BOFFS);

        unsigned ac[2][4], an[2][4];
        lda_frag(ac, As, 0);
#pragma unroll
        for (int kc = 0; kc < 4; kc++) {
            if (kc < 3) lda_frag(an, As, (kc + 1) * 8);
            int kr = kc * 8 + (lane & 3);
#pragma unroll
            for (int half = 0; half < 2; half++) {
                unsigned bb[4][2];
#pragma unroll
                for (int i = 0; i < 4; i++) {
                    int ncol = nb + (half * 4 + i) * 8 + (lane >> 2);
                    bb[i][0] = __float_as_uint(Bs[kr * 136 + ncol]);
                    bb[i][1] = __float_as_uint(Bs[(kr + 4) * 136 + ncol]);
                }
#pragma unroll
                for (int i = 0; i < 4; i++) {
                    int in_ = half * 4 + i;
#pragma unroll
                    for (int im = 0; im < 2; im++)
                        mma_tf32(acc[im][in_], ac[im][0], ac[im][1], ac[im][2],
                                 ac[im][3], bb[i][0], bb[i][1]);
                }
            }
            if (kc < 3) {
#pragma unroll
                for (int im = 0; im < 2; im++)
#pragma unroll
                    for (int j = 0; j < 4; j++) ac[im][j] = an[im][j];
            }
        }
    }
    __syncthreads();

    // -------- epilogue (smem-staged, coalesced) --------
    float* Cs = (float*)smc;
    if (EPI == 0) {
#pragma unroll 1
        for (int ch = 0; ch < 4; ch++) {
            __syncthreads();
            if (wm == ch) {
#pragma unroll
                for (int im = 0; im < 2; im++) {
                    int r0 = im * 16 + (lane >> 2);
#pragma unroll
                    for (int in_ = 0; in_ < 8; in_++) {
                        int cc = nb + in_ * 8 + (lane & 3) * 2;
                        Cs[r0 * 132 + cc]           = acc[im][in_][0];
                        Cs[r0 * 132 + cc + 1]       = acc[im][in_][1];
                        Cs[(r0 + 8) * 132 + cc]     = acc[im][in_][2];
                        Cs[(r0 + 8) * 132 + cc + 1] = acc[im][in_][3];
                    }
                }
            }
            __syncthreads();
            for (int t = tid; t < 32 * 128; t += 256) {
                int ml = t >> 7, n = t & 127;
                int m = m0 + ch * 32 + ml;
                if (MG && m >= M) continue;
                Cout[(size_t)m * N + n0 + n] = Cs[ml * 132 + n];
            }
        }
    } else {
#pragma unroll 1
        for (int ch = 0; ch < 4; ch++) {
            __syncthreads();
            if (wn == (ch >> 1)) {
                int inlo = (ch & 1) * 4;
#pragma unroll
                for (int im = 0; im < 2; im++) {
                    int mrow = mb + im * 16 + (lane >> 2);
#pragma unroll
                    for (int ii = 0; ii < 4; ii++) {
                        int in_ = inlo + ii;
                        int nl = in_ * 8 + (lane & 3) * 2 - (ch & 1) * 32;
                        Cs[nl * 132 + mrow]           = acc[im][in_][0];
                        Cs[(nl + 1) * 132 + mrow]     = acc[im][in_][1];
                        Cs[nl * 132 + mrow + 8]       = acc[im][in_][2];
                        Cs[(nl + 1) * 132 + mrow + 8] = acc[im][in_][3];
                    }
                }
            }
            __syncthreads();
            for (int t = tid; t < 32 * 128; t += 256) {
                int nl = t >> 7, ml = t & 127;
                int n = n0 + ch * 32 + nl;
                int m = m0 + ml;
                int b = m >> 12, s = m & (SP - 1);
                size_t addr = (size_t)b * CHN * SP + (size_t)n * SP + s;
                Cout[addr] = Cs[nl * 132 + ml] + bias[n] + resid[addr];
            }
        }
    }
}

// ---------------- tensor-core attention ----------------
// CTA: 128 query rows x one (b,h). 8 warps x 16 rows.
// S = Q K^T (tf32 mma), softmax in regs, P->smem (warp-private), O = P V (mma).
// smem: Qs[128][84] | Ks[80][84] | Vs[80][88]; Ps reuses Qs.
#define AT_SMEM 98048

__global__ void __launch_bounds__(256, 1) attn_mma()
{
    extern __shared__ float sm[];
    float* Qs = sm;              // [128][84]
    float* Ks = sm + 10752;      // [80][84]
    float* Vs = sm + 17472;      // [80][88]
    float* Ps = sm;              // reuse Q region

    int tid = threadIdx.x, lane = tid & 31, w = tid >> 5;
    int b = blockIdx.z, h = blockIdx.y;
    int q0 = blockIdx.x * 128;
    int mb = w * 16;
    uint32_t sb = smem_u32(sm);

    const float* qg = g_q + ((size_t)b * SP + q0) * INNER + h * HDIM;
    const float* kg = g_k + (size_t)b * TT * INNER + h * HDIM;
    const float* vg = g_v + (size_t)b * TT * INNER + h * HDIM;

#pragma unroll
    for (int i = 0; i < 10; i++) {               // Q: 128 rows x 20 chunks
        int cid = tid + i * 256;
        int row = cid / 20, ch = cid % 20;
        cp16(sb + (row * 84 + ch * 4) * 4, qg + (size_t)row * INNER + ch * 4, true);
    }
#pragma unroll
    for (int i = 0; i < 7; i++) {                // K: 77 rows x 20 chunks
        int cid = tid + i * 256;
        if (cid < 1540) {
            int row = cid / 20, ch = cid % 20;
            cp16(sb + 43008 + (row * 84 + ch * 4) * 4,
                 kg + (size_t)row * INNER + ch * 4, true);
        }
    }
#pragma unroll
    for (int i = 0; i < 7; i++) {                // V: 77 rows x 20 chunks
        int cid = tid + i * 256;
        if (cid < 1540) {
            int row = cid / 20, ch = cid % 20;
            cp16(sb + 69888 + (row * 88 + ch * 4) * 4,
                 vg + (size_t)row * INNER + ch * 4, true);
        }
    }
    CP_COMMIT();
    if (tid < 240) {                             // zero pad rows 77..79
        int row = 77 + tid / 80, col = tid % 80;
        Ks[row * 84 + col] = 0.f;
        Vs[row * 88 + col] = 0.f;
    }
    CP_WAIT0();
    __syncthreads();

    // ---- S = Q K^T ----
    float acc[10][4];
#pragma unroll
    for (int i = 0; i < 10; i++)
#pragma unroll
        for (int j = 0; j < 4; j++) acc[i][j] = 0.f;

#pragma unroll
    for (int k8 = 0; k8 < 10; k8++) {
        int kr = k8 * 8 + (lane & 3);
        int m = mb + (lane >> 2);
        unsigned a0 = __float_as_uint(Qs[m * 84 + kr]);
        unsigned a1 = __float_as_uint(Qs[(m + 8) * 84 + kr]);
        unsigned a2 = __float_as_uint(Qs[m * 84 + kr + 4]);
        unsigned a3 = __float_as_uint(Qs[(m + 8) * 84 + kr + 4]);
#pragma unroll
        for (int in_ = 0; in_ < 10; in_++) {
            int tcol = in_ * 8 + (lane >> 2);
            unsigned b0 = __float_as_uint(Ks[tcol * 84 + kr]);
            unsigned b1 = __float_as_uint(Ks[tcol * 84 + kr + 4]);
            mma_tf32(acc[in_], a0, a1, a2, a3, b0, b1);
        }
    }

    // ---- softmax (rows warp-private; reduce over quad lanes) ----
    const float scale = 0.11180339887498949f;
    int q2 = (lane & 3) * 2;
    int r = lane >> 2;
#pragma unroll
    for (int hf = 0; hf < 2; hf++) {
        float mx = -1e30f;
#pragma unroll
        for (int in_ = 0; in_ < 10; in_++) {
            int c0 = in_ * 8 + q2;
            float v0 = (c0     < TT) ? acc[in_][hf * 2]     * scale : -1e30f;
            float v1 = (c0 + 1 < TT) ? acc[in_][hf * 2 + 1] * scale : -1e30f;
            acc[in_][hf * 2] = v0; acc[in_][hf * 2 + 1] = v1;
            mx = fmaxf(mx, fmaxf(v0, v1));
        }
        mx = fmaxf(mx, __shfl_xor_sync(0xffffffffu, mx, 1));
        mx = fmaxf(mx, __shfl_xor_sync(0xffffffffu, mx, 2));
        float s = 0.f;
#pragma unroll
        for (int in_ = 0; in_ < 10; in_++) {
            int c0 = in_ * 8 + q2;
            float e0 = (c0     < TT) ? __expf(acc[in_][hf * 2]     - mx) : 0.f;
            float e1 = (c0 + 1 < TT) ? __expf(acc[in_][hf * 2 + 1] - mx) : 0.f;
            acc[in_][hf * 2] = e0; acc[in_][hf * 2 + 1] = e1;
            s += e0 + e1;
        }
        s += __shfl_xor_sync(0xffffffffu, s, 1);
        s += __shfl_xor_sync(0xffffffffu, s, 2);
        float inv = 1.f / s;
        int prow = mb + r + hf * 8;
#pragma unroll
        for (int in_ = 0; in_ < 10; in_++) {
            float2 p = make_float2(acc[in_][hf * 2] * inv, acc[in_][hf * 2 + 1] * inv);
            *(float2*)&Ps[prow * 84 + in_ * 8 + q2] = p;
        }
    }
    __syncwarp();

    // ---- O = P V ----
    float oc[10][4];
#pragma unroll
    for (int i = 0; i < 10; i++)
#pragma unroll
        for (int j = 0; j < 4; j++) oc[i][j] = 0.f;

#pragma unroll
    for (int k8 = 0; k8 < 10; k8++) {
        int kr = k8 * 8 + (lane & 3);
        int m = mb + (lane >> 2);
        unsigned a0 = __float_as_uint(Ps[m * 84 + kr]);
        unsigned a1 = __float_as_uint(Ps[(m + 8) * 84 + kr]);
        unsigned a2 = __float_as_uint(Ps[m * 84 + kr + 4]);
        unsigned a3 = __float_as_uint(Ps[(m + 8) * 84 + kr + 4]);
#pragma unroll
        for (int in_ = 0; in_ < 10; in_++) {
            int ncol = in_ * 8 + (lane >> 2);
            unsigned b0 = __float_as_uint(Vs[kr * 88 + ncol]);
            unsigned b1 = __float_as_uint(Vs[(kr + 4) * 88 + ncol]);
            mma_tf32(oc[in_], a0, a1, a2, a3, b0, b1);
        }
    }

    // ---- write O (32B-sector aligned float2 scatter) ----
    float* og = g_at + ((size_t)b * SP + q0 + mb) * INNER + h * HDIM;
#pragma unroll
    for (int in_ = 0; in_ < 10; in_++) {
        int c = in_ * 8 + q2;
        *(float2*)(og + (size_t)r * INNER + c)       = make_float2(oc[in_][0], oc[in_][1]);
        *(float2*)(og + (size_t)(r + 8) * INNER + c) = make_float2(oc[in_][2], oc[in_][3]);
    }
}

// ---------------- launch ----------------
extern "C" void kernel_launch(void* const* d_in, const int* in_sizes, int n_in,
                              void* d_out, int out_size)
{
    (void)in_sizes; (void)n_in; (void)out_size;
    const float* hs  = (const float*)d_in[0];
    const float* enc = (const float*)d_in[1];
    const float* lnw = (const float*)d_in[2];
    const float* lnb = (const float*)d_in[3];
    const float* wq  = (const float*)d_in[4];
    const float* wk  = (const float*)d_in[5];
    const float* wv  = (const float*)d_in[6];
    const float* wo  = (const float*)d_in[7];
    const float* bo  = (const float*)d_in[8];
    float* out = (float*)d_out;

    float *p_xn, *p_q, *p_k, *p_v, *p_at;
    cudaGetSymbolAddress((void**)&p_xn, g_xn);
    cudaGetSymbolAddress((void**)&p_q,  g_q);
    cudaGetSymbolAddress((void**)&p_k,  g_k);
    cudaGetSymbolAddress((void**)&p_v,  g_v);
    cudaGetSymbolAddress((void**)&p_at, g_at);

    cudaFuncSetAttribute(gemm_mm<0, 0, false>,
                         cudaFuncAttributeMaxDynamicSharedMemorySize, GSMEM);
    cudaFuncSetAttribute(gemm_mm<1, 0, true>,
                         cudaFuncAttributeMaxDynamicSharedMemorySize, GSMEM);
    cudaFuncSetAttribute(gemm_mm<1, 1, false>,
                         cudaFuncAttributeMaxDynamicSharedMemorySize, GSMEM);
    cudaFuncSetAttribute(attn_mma,
                         cudaFuncAttributeMaxDynamicSharedMemorySize, AT_SMEM);

    ln_kernel<<<dim3(SP / 256, BATCH), 256>>>(hs, lnw, lnb);

    // Q = xn @ wq
    gemm_mm<0, 0, false><<<dim3(INNER / 128, (BATCH * SP) / 128), 256, GSMEM>>>(
        p_xn, wq, p_q, BATCH * SP, INNER, CHN, 0, nullptr, nullptr);

    // K, V = enc @ wk / wv   (M = 1232, guarded)
    int mkv = (BATCH * TT + 127) / 128;
    gemm_mm<1, 0, true><<<dim3(INNER / 128, mkv), 256, GSMEM>>>(
        enc, wk, p_k, BATCH * TT, INNER, XDIM, XDIM, nullptr, nullptr);
    gemm_mm<1, 0, true><<<dim3(INNER / 128, mkv), 256, GSMEM>>>(
        enc, wv, p_v, BATCH * TT, INNER, XDIM, XDIM, nullptr, nullptr);

    // attention (tensor-core)
    attn_mma<<<dim3(SP / 128, NHE, BATCH), 256, AT_SMEM>>>();

    // out = at @ wo + bo + residual (transposed store)
    gemm_mm<1, 1, false><<<dim3(CHN / 128, (BATCH * SP) / 128), 256, GSMEM>>>(
        p_at, wo, out, BATCH * SP, CHN, INNER, INNER, bo, hs);
}

// round 6
// speedup vs baseline: 2.1918x; 1.0300x over previous
#include <cuda_runtime.h>
#include <cuda_bf16.h>
#include <math.h>
#include <stdint.h>

#define BATCH 16
#define CHN   640
#define SP    4096
#define TT    77
#define XDIM  768
#define NHE   8
#define HDIM  80
#define INNER 640

// ---------------- scratch ----------------
__device__ float g_q  [(size_t)BATCH * SP * INNER];
__device__ float g_k  [(size_t)BATCH * TT * INNER];
__device__ float g_v  [(size_t)BATCH * TT * INNER];
__device__ float g_at [(size_t)BATCH * SP * INNER];
__device__ float g_mu [(size_t)BATCH * SP];
__device__ float g_rs [(size_t)BATCH * SP];

// ---------------- helpers ----------------
__device__ __forceinline__ uint32_t smem_u32(const void* p) {
    uint32_t a;
    asm("{ .reg .u64 t; cvta.to.shared.u64 t, %1; cvt.u32.u64 %0, t; }"
        : "=r"(a) : "l"(p));
    return a;
}
__device__ __forceinline__ void cp16(uint32_t dst, const float* src, bool v) {
    int sz = v ? 16 : 0;
    asm volatile("cp.async.cg.shared.global [%0], [%1], 16, %2;"
                 :: "r"(dst), "l"(src), "r"(sz) : "memory");
}
#define CP_COMMIT() asm volatile("cp.async.commit_group;" ::: "memory")
#define CP_WAIT1()  asm volatile("cp.async.wait_group 1;" ::: "memory")
#define CP_WAIT0()  asm volatile("cp.async.wait_group 0;" ::: "memory")

__device__ __forceinline__ void mma_tf32(float c[4], unsigned a0, unsigned a1,
                                         unsigned a2, unsigned a3,
                                         unsigned b0, unsigned b1)
{
    asm volatile(
        "mma.sync.aligned.m16n8k8.row.col.f32.tf32.tf32.f32 "
        "{%0,%1,%2,%3},{%4,%5,%6,%7},{%8,%9},{%0,%1,%2,%3};"
        : "+f"(c[0]), "+f"(c[1]), "+f"(c[2]), "+f"(c[3])
        : "r"(a0), "r"(a1), "r"(a2), "r"(a3), "r"(b0), "r"(b1));
}

// ---------------- LN stats (mu, rstd per (b,s)) ----------------
__global__ void __launch_bounds__(256) ln_stats(const float* __restrict__ x)
{
    int s = blockIdx.x * 256 + threadIdx.x;
    int b = blockIdx.y;
    const float* xp = x + (size_t)b * CHN * SP + s;
    float sum = 0.f, sumsq = 0.f;
    for (int c = 0; c < CHN; c++) { float v = xp[(size_t)c * SP]; sum += v; sumsq += v * v; }
    float mu = sum * (1.0f / CHN);
    float var = sumsq * (1.0f / CHN) - mu * mu;
    g_mu[(size_t)b * SP + s] = mu;
    g_rs[(size_t)b * SP + s] = rsqrtf(var + 1e-6f);
}

// ---------------- pipelined mma.sync tf32 GEMM, BK=32 ----------------
// D[m][n] = sum_k A[m][k] * Bw[k][n]   (Bw row-major [K][N])
// ALOAD 0: A layout [b][k][s], m = b*4096+s       (smem [k][m] pitch 136)
// ALOAD 1: A row-major [M][lda]                   (smem [m][k] pitch 36)
// ALOAD 2: A = raw hs [b][k][s], normalize on the fly with mu/rs/lw/lb
// EPI 0: C[m][n];  EPI 1: out[b][n][s] + bias[n] + resid
#define BOFFS  18432
#define STG    35840
#define GSMEM  (3 * STG)      // 107520

template<int ALOAD, int EPI, bool MG>
__global__ void __launch_bounds__(256, 2)
gemm_mm(const float* __restrict__ A, const float* __restrict__ Bw,
        float* __restrict__ Cout, int M, int N, int K, int lda,
        const float* __restrict__ bias, const float* __restrict__ resid,
        const float* __restrict__ muP, const float* __restrict__ rsP,
        const float* __restrict__ lw, const float* __restrict__ lb)
{
    extern __shared__ char smc[];
    uint32_t sb = smem_u32(smc);

    int tid = threadIdx.x, lane = tid & 31, w = tid >> 5;
    int wm = w & 3, wn = w >> 2;
    int m0 = blockIdx.y * 128;
    int n0 = blockIdx.x * 128;
    int mb = wm * 32, nb = wn * 64;
    int NT = K >> 5;

    const float* Ab0 = A;
    if (ALOAD != 1)
        Ab0 = A + (size_t)(m0 >> 12) * CHN * SP + (m0 & (SP - 1));

    // fused-LN per-thread constants (ALOAD==2)
    float4 mu4 = make_float4(0.f, 0.f, 0.f, 0.f);
    float4 rs4 = make_float4(0.f, 0.f, 0.f, 0.f);
    int mc16 = (tid & 31) * 16;         // byte offset of this thread's float4 in m
    if (ALOAD == 2) {
        int mg = m0 + (tid & 31) * 4;
        mu4 = *(const float4*)(muP + mg);
        rs4 = *(const float4*)(rsP + mg);
    }

    float acc[2][8][4];
#pragma unroll
    for (int i = 0; i < 2; i++)
#pragma unroll
        for (int j = 0; j < 8; j++)
#pragma unroll
            for (int l = 0; l < 4; l++) acc[i][j][l] = 0.f;

    auto load_stage = [&](int slot, int k0) {
        uint32_t st = sb + slot * STG;
        if (ALOAD == 0) {
#pragma unroll
            for (int i = 0; i < 4; i++) {
                int cid = tid + i * 256;
                int kk = cid >> 5, mc = (cid & 31) * 4;
                cp16(st + kk * 544 + mc * 4,
                     Ab0 + (size_t)(k0 + kk) * SP + mc, true);
            }
        } else if (ALOAD == 2) {
#pragma unroll
            for (int i = 0; i < 4; i++) {
                int kk = (tid >> 5) + i * 8;
                float4 v = *(const float4*)(Ab0 + (size_t)(k0 + kk) * SP
                                            + (tid & 31) * 4);
                float wv = lw[k0 + kk], bv = lb[k0 + kk];
                float4 o;
                o.x = (v.x - mu4.x) * rs4.x * wv + bv;
                o.y = (v.y - mu4.y) * rs4.y * wv + bv;
                o.z = (v.z - mu4.z) * rs4.z * wv + bv;
                o.w = (v.w - mu4.w) * rs4.w * wv + bv;
                *(float4*)(smc + (st - sb) + kk * 544 + mc16) = o;
            }
        } else {
#pragma unroll
            for (int i = 0; i < 4; i++) {
                int cid = tid + i * 256;
                int row = cid >> 3, ch = cid & 7;
                bool v = !MG || (m0 + row) < M;
                cp16(st + row * 144 + ch * 16,
                     A + (size_t)(m0 + row) * lda + k0 + ch * 4, v);
            }
        }
        // B direct: [k][n] tile, pitch 136 floats (544B)
#pragma unroll
        for (int i = 0; i < 4; i++) {
            int cid = tid + i * 256;
            int row = cid >> 5, ch = cid & 31;
            cp16(st + BOFFS + row * 544 + ch * 16,
                 Bw + (size_t)(k0 + row) * N + n0 + ch * 4, true);
        }
    };

    auto lda_frag = [&](unsigned af[2][4], const float* As, int kc) {
        int kr = kc + (lane & 3);
#pragma unroll
        for (int im = 0; im < 2; im++) {
            int mrow = mb + im * 16 + (lane >> 2);
            if (ALOAD != 1) {
                af[im][0] = __float_as_uint(As[kr * 136 + mrow]);
                af[im][1] = __float_as_uint(As[kr * 136 + mrow + 8]);
                af[im][2] = __float_as_uint(As[(kr + 4) * 136 + mrow]);
                af[im][3] = __float_as_uint(As[(kr + 4) * 136 + mrow + 8]);
            } else {
                af[im][0] = __float_as_uint(As[mrow * 36 + kr]);
                af[im][1] = __float_as_uint(As[(mrow + 8) * 36 + kr]);
                af[im][2] = __float_as_uint(As[mrow * 36 + kr + 4]);
                af[im][3] = __float_as_uint(As[(mrow + 8) * 36 + kr + 4]);
            }
        }
    };

    load_stage(0, 0);  CP_COMMIT();
    load_stage(1, 32); CP_COMMIT();

    for (int t = 0; t < NT; t++) {
        if (t == NT - 1) CP_WAIT0(); else CP_WAIT1();
        __syncthreads();
        if (t + 2 < NT) { load_stage((t + 2) % 3, (t + 2) * 32); CP_COMMIT(); }

        int slot = t % 3;
        const float* As = (const float*)(smc + slot * STG);
        const float* Bs = (const float*)(smc + slot * STG + BOFFS);

        unsigned ac[2][4], an[2][4];
        lda_frag(ac, As, 0);
#pragma unroll
        for (int kc = 0; kc < 4; kc++) {
            if (kc < 3) lda_frag(an, As, (kc + 1) * 8);
            int kr = kc * 8 + (lane & 3);
#pragma unroll
            for (int half = 0; half < 2; half++) {
                unsigned bb[4][2];
#pragma unroll
                for (int i = 0; i < 4; i++) {
                    int ncol = nb + (half * 4 + i) * 8 + (lane >> 2);
                    bb[i][0] = __float_as_uint(Bs[kr * 136 + ncol]);
                    bb[i][1] = __float_as_uint(Bs[(kr + 4) * 136 + ncol]);
                }
#pragma unroll
                for (int i = 0; i < 4; i++) {
                    int in_ = half * 4 + i;
#pragma unroll
                    for (int im = 0; im < 2; im++)
                        mma_tf32(acc[im][in_], ac[im][0], ac[im][1], ac[im][2],
                                 ac[im][3], bb[i][0], bb[i][1]);
                }
            }
            if (kc < 3) {
#pragma unroll
                for (int im = 0; im < 2; im++)
#pragma unroll
                    for (int j = 0; j < 4; j++) ac[im][j] = an[im][j];
            }
        }
    }
    __syncthreads();

    // -------- epilogue --------
    float* Cs = (float*)smc;
    if (EPI == 0) {
#pragma unroll 1
        for (int ch = 0; ch < 4; ch++) {
            __syncthreads();
            if (wm == ch) {
#pragma unroll
                for (int im = 0; im < 2; im++) {
                    int r0 = im * 16 + (lane >> 2);
#pragma unroll
                    for (int in_ = 0; in_ < 8; in_++) {
                        int cc = nb + in_ * 8 + (lane & 3) * 2;
                        Cs[r0 * 132 + cc]           = acc[im][in_][0];
                        Cs[r0 * 132 + cc + 1]       = acc[im][in_][1];
                        Cs[(r0 + 8) * 132 + cc]     = acc[im][in_][2];
                        Cs[(r0 + 8) * 132 + cc + 1] = acc[im][in_][3];
                    }
                }
            }
            __syncthreads();
            for (int t = tid; t < 32 * 128; t += 256) {
                int ml = t >> 7, n = t & 127;
                int m = m0 + ch * 32 + ml;
                if (MG && m >= M) continue;
                Cout[(size_t)m * N + n0 + n] = Cs[ml * 132 + n];
            }
        }
    } else {
#pragma unroll 1
        for (int ch = 0; ch < 4; ch++) {
            __syncthreads();
            if (wn == (ch >> 1)) {
                int inlo = (ch & 1) * 4;
#pragma unroll
                for (int im = 0; im < 2; im++) {
                    int mrow = mb + im * 16 + (lane >> 2);
#pragma unroll
                    for (int ii = 0; ii < 4; ii++) {
                        int in_ = inlo + ii;
                        int nl = in_ * 8 + (lane & 3) * 2 - (ch & 1) * 32;
                        Cs[nl * 132 + mrow]           = acc[im][in_][0];
                        Cs[(nl + 1) * 132 + mrow]     = acc[im][in_][1];
                        Cs[nl * 132 + mrow + 8]       = acc[im][in_][2];
                        Cs[(nl + 1) * 132 + mrow + 8] = acc[im][in_][3];
                    }
                }
            }
            __syncthreads();
            for (int t = tid; t < 32 * 128; t += 256) {
                int nl = t >> 7, ml = t & 127;
                int n = n0 + ch * 32 + nl;
                int m = m0 + ml;
                int b = m >> 12, s = m & (SP - 1);
                size_t addr = (size_t)b * CHN * SP + (size_t)n * SP + s;
                Cout[addr] = Cs[nl * 132 + ml] + bias[n] + resid[addr];
            }
        }
    }
}

// ---------------- tensor-core attention v2: 2 CTAs/SM ----------------
// smem only K[80][84] + V[80][88] = 55,040B. Q fragments LDG'd to regs.
// P never hits smem: PV A-fragments rebuilt from S-accums via warp shuffles.
#define AT_SMEM 55040

__global__ void __launch_bounds__(256, 2) attn_mma()
{
    extern __shared__ float sm[];
    float* Ks = sm;              // [80][84]
    float* Vs = sm + 6720;       // [80][88]

    int tid = threadIdx.x, lane = tid & 31, w = tid >> 5;
    int b = blockIdx.z, h = blockIdx.y;
    int q0 = blockIdx.x * 128;
    int mb = w * 16;
    int r = lane >> 2, q = lane & 3, q2 = q * 2;
    uint32_t sb = smem_u32(sm);

    const float* kg = g_k + (size_t)b * TT * INNER + h * HDIM;
    const float* vg = g_v + (size_t)b * TT * INNER + h * HDIM;

#pragma unroll
    for (int i = 0; i < 7; i++) {
        int cid = tid + i * 256;
        if (cid < 1540) {
            int row = cid / 20, ch = cid % 20;
            cp16(sb + (row * 84 + ch * 4) * 4, kg + (size_t)row * INNER + ch * 4, true);
            cp16(sb + (6720 + row * 88 + ch * 4) * 4, vg + (size_t)row * INNER + ch * 4, true);
        }
    }
    CP_COMMIT();

    // Q fragments straight from gmem
    const float* qg = g_q + ((size_t)b * SP + q0 + mb) * INNER + h * HDIM;
    float qf[10][4];
#pragma unroll
    for (int k8 = 0; k8 < 10; k8++) {
        int c = k8 * 8 + q;
        qf[k8][0] = qg[(size_t)r * INNER + c];
        qf[k8][1] = qg[(size_t)(r + 8) * INNER + c];
        qf[k8][2] = qg[(size_t)r * INNER + c + 4];
        qf[k8][3] = qg[(size_t)(r + 8) * INNER + c + 4];
    }

    if (tid < 240) {                 // zero pad rows 77..79
        int row = 77 + tid / 80, col = tid % 80;
        Ks[row * 84 + col] = 0.f;
        Vs[row * 88 + col] = 0.f;
    }
    CP_WAIT0();
    __syncthreads();

    // ---- S = Q K^T ----
    float acc[10][4];
#pragma unroll
    for (int i = 0; i < 10; i++)
#pragma unroll
        for (int j = 0; j < 4; j++) acc[i][j] = 0.f;

#pragma unroll
    for (int k8 = 0; k8 < 10; k8++) {
        int kr = k8 * 8 + q;
        unsigned a0 = __float_as_uint(qf[k8][0]);
        unsigned a1 = __float_as_uint(qf[k8][1]);
        unsigned a2 = __float_as_uint(qf[k8][2]);
        unsigned a3 = __float_as_uint(qf[k8][3]);
#pragma unroll
        for (int in_ = 0; in_ < 10; in_++) {
            int tcol = in_ * 8 + r;
            unsigned b0 = __float_as_uint(Ks[tcol * 84 + kr]);
            unsigned b1 = __float_as_uint(Ks[tcol * 84 + kr + 4]);
            mma_tf32(acc[in_], a0, a1, a2, a3, b0, b1);
        }
    }

    // ---- softmax (un-normalized; keep 1/sum per row) ----
    const float scale = 0.11180339887498949f;
    float invs[2];
#pragma unroll
    for (int hf = 0; hf < 2; hf++) {
        float mx = -1e30f;
#pragma unroll
        for (int in_ = 0; in_ < 10; in_++) {
            int c0 = in_ * 8 + q2;
            float v0 = (c0     < TT) ? acc[in_][hf * 2]     * scale : -1e30f;
            float v1 = (c0 + 1 < TT) ? acc[in_][hf * 2 + 1] * scale : -1e30f;
            acc[in_][hf * 2] = v0; acc[in_][hf * 2 + 1] = v1;
            mx = fmaxf(mx, fmaxf(v0, v1));
        }
        mx = fmaxf(mx, __shfl_xor_sync(0xffffffffu, mx, 1));
        mx = fmaxf(mx, __shfl_xor_sync(0xffffffffu, mx, 2));
        float s = 0.f;
#pragma unroll
        for (int in_ = 0; in_ < 10; in_++) {
            int c0 = in_ * 8 + q2;
            float e0 = (c0     < TT) ? __expf(acc[in_][hf * 2]     - mx) : 0.f;
            float e1 = (c0 + 1 < TT) ? __expf(acc[in_][hf * 2 + 1] - mx) : 0.f;
            acc[in_][hf * 2] = e0; acc[in_][hf * 2 + 1] = e1;
            s += e0 + e1;
        }
        s += __shfl_xor_sync(0xffffffffu, s, 1);
        s += __shfl_xor_sync(0xffffffffu, s, 2);
        invs[hf] = 1.f / s;
    }

    // ---- O = P V  (P fragments via shuffles from acc) ----
    float oc[10][4];
#pragma unroll
    for (int i = 0; i < 10; i++)
#pragma unroll
        for (int j = 0; j < 4; j++) oc[i][j] = 0.f;

    int S0 = (r << 2) | (q >> 1);
    int S2 = S0 + 2;
    bool odd = (q & 1) != 0;
#pragma unroll
    for (int k8 = 0; k8 < 10; k8++) {
        float v0 = __shfl_sync(0xffffffffu, acc[k8][0], S0);
        float v1 = __shfl_sync(0xffffffffu, acc[k8][1], S0);
        float v2 = __shfl_sync(0xffffffffu, acc[k8][2], S0);
        float v3 = __shfl_sync(0xffffffffu, acc[k8][3], S0);
        float u0 = __shfl_sync(0xffffffffu, acc[k8][0], S2);
        float u1 = __shfl_sync(0xffffffffu, acc[k8][1], S2);
        float u2 = __shfl_sync(0xffffffffu, acc[k8][2], S2);
        float u3 = __shfl_sync(0xffffffffu, acc[k8][3], S2);
        unsigned a0 = __float_as_uint(odd ? v1 : v0);
        unsigned a1 = __float_as_uint(odd ? v3 : v2);
        unsigned a2 = __float_as_uint(odd ? u1 : u0);
        unsigned a3 = __float_as_uint(odd ? u3 : u2);
        int kr = k8 * 8 + q;
#pragma unroll
        for (int in_ = 0; in_ < 10; in_++) {
            int ncol = in_ * 8 + r;
            unsigned b0 = __float_as_uint(Vs[kr * 88 + ncol]);
            unsigned b1 = __float_as_uint(Vs[(kr + 4) * 88 + ncol]);
            mma_tf32(oc[in_], a0, a1, a2, a3, b0, b1);
        }
    }

    // ---- scale by 1/sum and write ----
    float* og = g_at + ((size_t)b * SP + q0 + mb) * INNER + h * HDIM;
#pragma unroll
    for (int in_ = 0; in_ < 10; in_++) {
        int c = in_ * 8 + q2;
        *(float2*)(og + (size_t)r * INNER + c) =
            make_float2(oc[in_][0] * invs[0], oc[in_][1] * invs[0]);
        *(float2*)(og + (size_t)(r + 8) * INNER + c) =
            make_float2(oc[in_][2] * invs[1], oc[in_][3] * invs[1]);
    }
}

// ---------------- launch ----------------
extern "C" void kernel_launch(void* const* d_in, const int* in_sizes, int n_in,
                              void* d_out, int out_size)
{
    (void)in_sizes; (void)n_in; (void)out_size;
    const float* hs  = (const float*)d_in[0];
    const float* enc = (const float*)d_in[1];
    const float* lnw = (const float*)d_in[2];
    const float* lnb = (const float*)d_in[3];
    const float* wq  = (const float*)d_in[4];
    const float* wk  = (const float*)d_in[5];
    const float* wv  = (const float*)d_in[6];
    const float* wo  = (const float*)d_in[7];
    const float* bo  = (const float*)d_in[8];
    float* out = (float*)d_out;

    float *p_q, *p_k, *p_v, *p_at, *p_mu, *p_rs;
    cudaGetSymbolAddress((void**)&p_q,  g_q);
    cudaGetSymbolAddress((void**)&p_k,  g_k);
    cudaGetSymbolAddress((void**)&p_v,  g_v);
    cudaGetSymbolAddress((void**)&p_at, g_at);
    cudaGetSymbolAddress((void**)&p_mu, g_mu);
    cudaGetSymbolAddress((void**)&p_rs, g_rs);

    cudaFuncSetAttribute(gemm_mm<2, 0, false>,
                         cudaFuncAttributeMaxDynamicSharedMemorySize, GSMEM);
    cudaFuncSetAttribute(gemm_mm<1, 0, true>,
                         cudaFuncAttributeMaxDynamicSharedMemorySize, GSMEM);
    cudaFuncSetAttribute(gemm_mm<1, 1, false>,
                         cudaFuncAttributeMaxDynamicSharedMemorySize, GSMEM);
    cudaFuncSetAttribute(attn_mma,
                         cudaFuncAttributeMaxDynamicSharedMemorySize, AT_SMEM);

    // per-row LN statistics
    ln_stats<<<dim3(SP / 256, BATCH), 256>>>(hs);

    // Q = LN(hs) @ wq (normalization fused into A loader)
    gemm_mm<2, 0, false><<<dim3(INNER / 128, (BATCH * SP) / 128), 256, GSMEM>>>(
        hs, wq, p_q, BATCH * SP, INNER, CHN, 0, nullptr, nullptr,
        p_mu, p_rs, lnw, lnb);

    // K, V = enc @ wk / wv
    int mkv = (BATCH * TT + 127) / 128;
    gemm_mm<1, 0, true><<<dim3(INNER / 128, mkv), 256, GSMEM>>>(
        enc, wk, p_k, BATCH * TT, INNER, XDIM, XDIM, nullptr, nullptr,
        nullptr, nullptr, nullptr, nullptr);
    gemm_mm<1, 0, true><<<dim3(INNER / 128, mkv), 256, GSMEM>>>(
        enc, wv, p_v, BATCH * TT, INNER, XDIM, XDIM, nullptr, nullptr,
        nullptr, nullptr, nullptr, nullptr);

    // attention
    attn_mma<<<dim3(SP / 128, NHE, BATCH), 256, AT_SMEM>>>();

    // out = at @ wo + bo + residual (transposed store)
    gemm_mm<1, 1, false><<<dim3(CHN / 128, (BATCH * SP) / 128), 256, GSMEM>>>(
        p_at, wo, out, BATCH * SP, CHN, INNER, INNER, bo, hs,
        nullptr, nullptr, nullptr, nullptr);
}

// round 7
// speedup vs baseline: 3.4097x; 1.5557x over previous
#include <cuda_runtime.h>
#include <cuda_fp16.h>
#include <math.h>
#include <stdint.h>

#define BATCH 16
#define CHN   640
#define SP    4096
#define TT    77
#define XDIM  768
#define NHE   8
#define HDIM  80
#define INNER 640

// ---------------- scratch ----------------
__device__ float  g_q   [(size_t)BATCH * SP * INNER];   // fp32 (attn input)
__device__ float  g_k   [(size_t)BATCH * TT * INNER];
__device__ float  g_v   [(size_t)BATCH * TT * INNER];
__device__ __half g_x16 [(size_t)BATCH * SP * CHN];     // LN(hs) [b][s][c]
__device__ __half g_at16[(size_t)BATCH * SP * INNER];   // attn out
__device__ __half g_e16 [(size_t)BATCH * TT * XDIM];
__device__ __half g_wq16[(size_t)INNER * CHN];          // [N][K]
__device__ __half g_wk16[(size_t)INNER * XDIM];
__device__ __half g_wv16[(size_t)INNER * XDIM];
__device__ __half g_wo16[(size_t)CHN * INNER];
__device__ float  g_mu  [(size_t)BATCH * SP];
__device__ float  g_rs  [(size_t)BATCH * SP];

// ---------------- helpers ----------------
__device__ __forceinline__ uint32_t smem_u32(const void* p) {
    uint32_t a;
    asm("{ .reg .u64 t; cvta.to.shared.u64 t, %1; cvt.u32.u64 %0, t; }"
        : "=r"(a) : "l"(p));
    return a;
}
__device__ __forceinline__ void cp16(uint32_t dst, const void* src, bool v) {
    int sz = v ? 16 : 0;
    asm volatile("cp.async.cg.shared.global [%0], [%1], 16, %2;"
                 :: "r"(dst), "l"(src), "r"(sz) : "memory");
}
#define CP_COMMIT() asm volatile("cp.async.commit_group;" ::: "memory")
#define CP_WAIT1()  asm volatile("cp.async.wait_group 1;" ::: "memory")
#define CP_WAIT0()  asm volatile("cp.async.wait_group 0;" ::: "memory")

__device__ __forceinline__ void mma_tf32(float c[4], unsigned a0, unsigned a1,
                                         unsigned a2, unsigned a3,
                                         unsigned b0, unsigned b1)
{
    asm volatile(
        "mma.sync.aligned.m16n8k8.row.col.f32.tf32.tf32.f32 "
        "{%0,%1,%2,%3},{%4,%5,%6,%7},{%8,%9},{%0,%1,%2,%3};"
        : "+f"(c[0]), "+f"(c[1]), "+f"(c[2]), "+f"(c[3])
        : "r"(a0), "r"(a1), "r"(a2), "r"(a3), "r"(b0), "r"(b1));
}
__device__ __forceinline__ void mma_f16(float c[4], unsigned a0, unsigned a1,
                                        unsigned a2, unsigned a3,
                                        unsigned b0, unsigned b1)
{
    asm volatile(
        "mma.sync.aligned.m16n8k16.row.col.f32.f16.f16.f32 "
        "{%0,%1,%2,%3},{%4,%5,%6,%7},{%8,%9},{%0,%1,%2,%3};"
        : "+f"(c[0]), "+f"(c[1]), "+f"(c[2]), "+f"(c[3])
        : "r"(a0), "r"(a1), "r"(a2), "r"(a3), "r"(b0), "r"(b1));
}

// ---------------- LN stats ----------------
__global__ void __launch_bounds__(256) ln_stats(const float* __restrict__ x)
{
    int s = blockIdx.x * 256 + threadIdx.x;
    int b = blockIdx.y;
    const float* xp = x + (size_t)b * CHN * SP + s;
    float sum = 0.f, sumsq = 0.f;
    for (int c = 0; c < CHN; c++) { float v = xp[(size_t)c * SP]; sum += v; sumsq += v * v; }
    float mu = sum * (1.0f / CHN);
    float var = sumsq * (1.0f / CHN) - mu * mu;
    g_mu[(size_t)b * SP + s] = mu;
    g_rs[(size_t)b * SP + s] = rsqrtf(var + 1e-6f);
}

// ---------------- normalize + transpose -> fp16 [b][s][c] ----------------
__global__ void __launch_bounds__(256) ln_t16(const float* __restrict__ x,
                                              const float* __restrict__ lw,
                                              const float* __restrict__ lb)
{
    __shared__ float t[32][33];
    int s0 = blockIdx.x * 32, c0 = blockIdx.y * 32, b = blockIdx.z;
    int xl = threadIdx.x & 31, y = (threadIdx.x >> 5) * 4;
#pragma unroll
    for (int i = 0; i < 4; i++)
        t[y + i][xl] = x[((size_t)b * CHN + c0 + y + i) * SP + s0 + xl];
    __syncthreads();
    float wv = lw[c0 + xl], bv = lb[c0 + xl];
#pragma unroll
    for (int i = 0; i < 4; i++) {
        int s = s0 + y + i;
        float mu = g_mu[(size_t)b * SP + s];
        float rs = g_rs[(size_t)b * SP + s];
        float v = (t[xl][y + i] - mu) * rs * wv + bv;
        g_x16[((size_t)b * SP + s) * CHN + c0 + xl] = __float2half_rn(v);
    }
}

// ---------------- weight transpose+cvt [R][C] fp32 -> [C][R] fp16 ----------------
__global__ void __launch_bounds__(256) cvt_w_t(const float* __restrict__ in,
                                               __half* __restrict__ out, int R, int C)
{
    __shared__ float t[32][33];
    int c0 = blockIdx.x * 32, r0 = blockIdx.y * 32;
    int xl = threadIdx.x & 31, y = (threadIdx.x >> 5) * 4;
#pragma unroll
    for (int i = 0; i < 4; i++)
        t[y + i][xl] = in[(size_t)(r0 + y + i) * C + c0 + xl];
    __syncthreads();
#pragma unroll
    for (int i = 0; i < 4; i++)
        out[(size_t)(c0 + y + i) * R + r0 + xl] = __float2half_rn(t[xl][y + i]);
}

// ---------------- elementwise cvt ----------------
__global__ void __launch_bounds__(256) cvt16(const float* __restrict__ in,
                                             __half* __restrict__ out, int n)
{
    int i = blockIdx.x * 256 + threadIdx.x;
    if (i < n) out[i] = __float2half_rn(in[i]);
}

// ---------------- fp16 mma GEMM: D = A[M][K] * Bt[N][K]^T ----------------
// A, Bt fp16 row-major (K contiguous). 128x128x32 tiles, 3-stage cp.async.
// EPI 0: C[m][n] fp32;  EPI 1: out[b][n][s] + bias[n] + resid (fp32)
#define HBOFF  10240
#define HSTG   20480
#define HGSMEM (3 * HSTG)     // 61440

template<int EPI, bool MG>
__global__ void __launch_bounds__(256, 2)
gemm_h(const __half* __restrict__ A, const __half* __restrict__ Bt,
       float* __restrict__ Cout, int M, int N, int K, int lda,
       const float* __restrict__ bias, const float* __restrict__ resid)
{
    extern __shared__ char smc[];
    uint32_t sb = smem_u32(smc);

    int tid = threadIdx.x, lane = tid & 31, w = tid >> 5;
    int r = lane >> 2, q = lane & 3;
    int wm = w & 3, wn = w >> 2;
    int m0 = blockIdx.y * 128;
    int n0 = blockIdx.x * 128;
    int mb = wm * 32, nb = wn * 64;
    int NT = K >> 5;

    float acc[2][8][4];
#pragma unroll
    for (int i = 0; i < 2; i++)
#pragma unroll
        for (int j = 0; j < 8; j++)
#pragma unroll
            for (int l = 0; l < 4; l++) acc[i][j][l] = 0.f;

    auto load_stage = [&](int slot, int k0) {
        uint32_t st = sb + slot * HSTG;
#pragma unroll
        for (int i = 0; i < 2; i++) {
            int cid = tid + i * 256;
            int row = cid >> 2, ch = cid & 3;
            bool v = !MG || (m0 + row) < M;
            cp16(st + row * 80 + ch * 16,
                 A + (size_t)(m0 + row) * lda + k0 + ch * 8, v);
        }
#pragma unroll
        for (int i = 0; i < 2; i++) {
            int cid = tid + i * 256;
            int row = cid >> 2, ch = cid & 3;
            cp16(st + HBOFF + row * 80 + ch * 16,
                 Bt + (size_t)(n0 + row) * K + k0 + ch * 8, true);
        }
    };

    auto lda_frag = [&](unsigned af[2][4], const __half* As, int kb) {
        int kof = kb + 2 * q;
#pragma unroll
        for (int im = 0; im < 2; im++) {
            int mrow = mb + im * 16 + r;
            af[im][0] = *(const unsigned*)&As[mrow * 40 + kof];
            af[im][1] = *(const unsigned*)&As[(mrow + 8) * 40 + kof];
            af[im][2] = *(const unsigned*)&As[mrow * 40 + kof + 8];
            af[im][3] = *(const unsigned*)&As[(mrow + 8) * 40 + kof + 8];
        }
    };

    load_stage(0, 0);  CP_COMMIT();
    load_stage(1, 32); CP_COMMIT();

    for (int t = 0; t < NT; t++) {
        if (t == NT - 1) CP_WAIT0(); else CP_WAIT1();
        __syncthreads();
        if (t + 2 < NT) { load_stage((t + 2) % 3, (t + 2) * 32); CP_COMMIT(); }

        int slot = t % 3;
        const __half* As = (const __half*)(smc + slot * HSTG);
        const __half* Bs = (const __half*)(smc + slot * HSTG + HBOFF);

        unsigned ac[2][4], an[2][4];
        lda_frag(ac, As, 0);
#pragma unroll
        for (int kc = 0; kc < 2; kc++) {
            if (kc == 0) lda_frag(an, As, 16);
            int kof = kc * 16 + 2 * q;
#pragma unroll
            for (int half_ = 0; half_ < 2; half_++) {
                unsigned bb[4][2];
#pragma unroll
                for (int i = 0; i < 4; i++) {
                    int ncol = nb + (half_ * 4 + i) * 8 + r;
                    bb[i][0] = *(const unsigned*)&Bs[ncol * 40 + kof];
                    bb[i][1] = *(const unsigned*)&Bs[ncol * 40 + kof + 8];
                }
#pragma unroll
                for (int i = 0; i < 4; i++) {
                    int in_ = half_ * 4 + i;
#pragma unroll
                    for (int im = 0; im < 2; im++)
                        mma_f16(acc[im][in_], ac[im][0], ac[im][1], ac[im][2],
                                ac[im][3], bb[i][0], bb[i][1]);
                }
            }
            if (kc == 0) {
#pragma unroll
                for (int im = 0; im < 2; im++)
#pragma unroll
                    for (int j = 0; j < 4; j++) ac[im][j] = an[im][j];
            }
        }
    }
    __syncthreads();

    // -------- epilogue --------
    float* Cs = (float*)smc;
    if (EPI == 0) {
#pragma unroll 1
        for (int ch = 0; ch < 4; ch++) {
            __syncthreads();
            if (wm == ch) {
#pragma unroll
                for (int im = 0; im < 2; im++) {
                    int r0 = im * 16 + r;
#pragma unroll
                    for (int in_ = 0; in_ < 8; in_++) {
                        int cc = nb + in_ * 8 + q * 2;
                        Cs[r0 * 132 + cc]           = acc[im][in_][0];
                        Cs[r0 * 132 + cc + 1]       = acc[im][in_][1];
                        Cs[(r0 + 8) * 132 + cc]     = acc[im][in_][2];
                        Cs[(r0 + 8) * 132 + cc + 1] = acc[im][in_][3];
                    }
                }
            }
            __syncthreads();
            for (int t = tid; t < 32 * 128; t += 256) {
                int ml = t >> 7, n = t & 127;
                int m = m0 + ch * 32 + ml;
                if (MG && m >= M) continue;
                Cout[(size_t)m * N + n0 + n] = Cs[ml * 132 + n];
            }
        }
    } else {
#pragma unroll 1
        for (int ch = 0; ch < 4; ch++) {
            __syncthreads();
            if (wn == (ch >> 1)) {
                int inlo = (ch & 1) * 4;
#pragma unroll
                for (int im = 0; im < 2; im++) {
                    int mrow = mb + im * 16 + r;
#pragma unroll
                    for (int ii = 0; ii < 4; ii++) {
                        int in_ = inlo + ii;
                        int nl = in_ * 8 + q * 2 - (ch & 1) * 32;
                        Cs[nl * 132 + mrow]           = acc[im][in_][0];
                        Cs[(nl + 1) * 132 + mrow]     = acc[im][in_][1];
                        Cs[nl * 132 + mrow + 8]       = acc[im][in_][2];
                        Cs[(nl + 1) * 132 + mrow + 8] = acc[im][in_][3];
                    }
                }
            }
            __syncthreads();
            for (int t = tid; t < 32 * 128; t += 256) {
                int nl = t >> 7, ml = t & 127;
                int n = n0 + ch * 32 + nl;
                int m = m0 + ml;
                int b = m >> 12, s = m & (SP - 1);
                size_t addr = (size_t)b * CHN * SP + (size_t)n * SP + s;
                Cout[addr] = Cs[nl * 132 + ml] + bias[n] + resid[addr];
            }
        }
    }
}

// ---------------- tensor-core attention (tf32), half2 output ----------------
#define AT_SMEM 55040

__global__ void __launch_bounds__(256, 2) attn_mma()
{
    extern __shared__ float sm[];
    float* Ks = sm;              // [80][84]
    float* Vs = sm + 6720;       // [80][88]

    int tid = threadIdx.x, lane = tid & 31, w = tid >> 5;
    int b = blockIdx.z, h = blockIdx.y;
    int q0 = blockIdx.x * 128;
    int mb = w * 16;
    int r = lane >> 2, q = lane & 3, q2 = q * 2;
    uint32_t sb = smem_u32(sm);

    const float* kg = g_k + (size_t)b * TT * INNER + h * HDIM;
    const float* vg = g_v + (size_t)b * TT * INNER + h * HDIM;

#pragma unroll
    for (int i = 0; i < 7; i++) {
        int cid = tid + i * 256;
        if (cid < 1540) {
            int row = cid / 20, ch = cid % 20;
            cp16(sb + (row * 84 + ch * 4) * 4, kg + (size_t)row * INNER + ch * 4, true);
            cp16(sb + (6720 + row * 88 + ch * 4) * 4, vg + (size_t)row * INNER + ch * 4, true);
        }
    }
    CP_COMMIT();

    const float* qg = g_q + ((size_t)b * SP + q0 + mb) * INNER + h * HDIM;
    float qf[10][4];
#pragma unroll
    for (int k8 = 0; k8 < 10; k8++) {
        int c = k8 * 8 + q;
        qf[k8][0] = qg[(size_t)r * INNER + c];
        qf[k8][1] = qg[(size_t)(r + 8) * INNER + c];
        qf[k8][2] = qg[(size_t)r * INNER + c + 4];
        qf[k8][3] = qg[(size_t)(r + 8) * INNER + c + 4];
    }

    if (tid < 240) {
        int row = 77 + tid / 80, col = tid % 80;
        Ks[row * 84 + col] = 0.f;
        Vs[row * 88 + col] = 0.f;
    }
    CP_WAIT0();
    __syncthreads();

    float acc[10][4];
#pragma unroll
    for (int i = 0; i < 10; i++)
#pragma unroll
        for (int j = 0; j < 4; j++) acc[i][j] = 0.f;

#pragma unroll
    for (int k8 = 0; k8 < 10; k8++) {
        int kr = k8 * 8 + q;
        unsigned a0 = __float_as_uint(qf[k8][0]);
        unsigned a1 = __float_as_uint(qf[k8][1]);
        unsigned a2 = __float_as_uint(qf[k8][2]);
        unsigned a3 = __float_as_uint(qf[k8][3]);
#pragma unroll
        for (int in_ = 0; in_ < 10; in_++) {
            int tcol = in_ * 8 + r;
            unsigned b0 = __float_as_uint(Ks[tcol * 84 + kr]);
            unsigned b1 = __float_as_uint(Ks[tcol * 84 + kr + 4]);
            mma_tf32(acc[in_], a0, a1, a2, a3, b0, b1);
        }
    }

    const float scale = 0.11180339887498949f;
    float invs[2];
#pragma unroll
    for (int hf = 0; hf < 2; hf++) {
        float mx = -1e30f;
#pragma unroll
        for (int in_ = 0; in_ < 10; in_++) {
            int c0 = in_ * 8 + q2;
            float v0 = (c0     < TT) ? acc[in_][hf * 2]     * scale : -1e30f;
            float v1 = (c0 + 1 < TT) ? acc[in_][hf * 2 + 1] * scale : -1e30f;
            acc[in_][hf * 2] = v0; acc[in_][hf * 2 + 1] = v1;
            mx = fmaxf(mx, fmaxf(v0, v1));
        }
        mx = fmaxf(mx, __shfl_xor_sync(0xffffffffu, mx, 1));
        mx = fmaxf(mx, __shfl_xor_sync(0xffffffffu, mx, 2));
        float s = 0.f;
#pragma unroll
        for (int in_ = 0; in_ < 10; in_++) {
            int c0 = in_ * 8 + q2;
            float e0 = (c0     < TT) ? __expf(acc[in_][hf * 2]     - mx) : 0.f;
            float e1 = (c0 + 1 < TT) ? __expf(acc[in_][hf * 2 + 1] - mx) : 0.f;
            acc[in_][hf * 2] = e0; acc[in_][hf * 2 + 1] = e1;
            s += e0 + e1;
        }
        s += __shfl_xor_sync(0xffffffffu, s, 1);
        s += __shfl_xor_sync(0xffffffffu, s, 2);
        invs[hf] = 1.f / s;
    }

    float oc[10][4];
#pragma unroll
    for (int i = 0; i < 10; i++)
#pragma unroll
        for (int j = 0; j < 4; j++) oc[i][j] = 0.f;

    int S0 = (r << 2) | (q >> 1);
    int S2 = S0 + 2;
    bool odd = (q & 1) != 0;
#pragma unroll
    for (int k8 = 0; k8 < 10; k8++) {
        float v0 = __shfl_sync(0xffffffffu, acc[k8][0], S0);
        float v1 = __shfl_sync(0xffffffffu, acc[k8][1], S0);
        float v2 = __shfl_sync(0xffffffffu, acc[k8][2], S0);
        float v3 = __shfl_sync(0xffffffffu, acc[k8][3], S0);
        float u0 = __shfl_sync(0xffffffffu, acc[k8][0], S2);
        float u1 = __shfl_sync(0xffffffffu, acc[k8][1], S2);
        float u2 = __shfl_sync(0xffffffffu, acc[k8][2], S2);
        float u3 = __shfl_sync(0xffffffffu, acc[k8][3], S2);
        unsigned a0 = __float_as_uint(odd ? v1 : v0);
        unsigned a1 = __float_as_uint(odd ? v3 : v2);
        unsigned a2 = __float_as_uint(odd ? u1 : u0);
        unsigned a3 = __float_as_uint(odd ? u3 : u2);
        int kr = k8 * 8 + q;
#pragma unroll
        for (int in_ = 0; in_ < 10; in_++) {
            int ncol = in_ * 8 + r;
            unsigned b0 = __float_as_uint(Vs[kr * 88 + ncol]);
            unsigned b1 = __float_as_uint(Vs[(kr + 4) * 88 + ncol]);
            mma_tf32(oc[in_], a0, a1, a2, a3, b0, b1);
        }
    }

    __half* og = g_at16 + ((size_t)b * SP + q0 + mb) * INNER + h * HDIM;
#pragma unroll
    for (int in_ = 0; in_ < 10; in_++) {
        int c = in_ * 8 + q2;
        *(__half2*)(og + (size_t)r * INNER + c) =
            __floats2half2_rn(oc[in_][0] * invs[0], oc[in_][1] * invs[0]);
        *(__half2*)(og + (size_t)(r + 8) * INNER + c) =
            __floats2half2_rn(oc[in_][2] * invs[1], oc[in_][3] * invs[1]);
    }
}

// ---------------- launch ----------------
extern "C" void kernel_launch(void* const* d_in, const int* in_sizes, int n_in,
                              void* d_out, int out_size)
{
    (void)in_sizes; (void)n_in; (void)out_size;
    const float* hs  = (const float*)d_in[0];
    const float* enc = (const float*)d_in[1];
    const float* lnw = (const float*)d_in[2];
    const float* lnb = (const float*)d_in[3];
    const float* wq  = (const float*)d_in[4];
    const float* wk  = (const float*)d_in[5];
    const float* wv  = (const float*)d_in[6];
    const float* wo  = (const float*)d_in[7];
    const float* bo  = (const float*)d_in[8];
    float* out = (float*)d_out;

    float *p_q, *p_k, *p_v;
    __half *p_x16, *p_at16, *p_e16, *p_wq16, *p_wk16, *p_wv16, *p_wo16;
    cudaGetSymbolAddress((void**)&p_q,    g_q);
    cudaGetSymbolAddress((void**)&p_k,    g_k);
    cudaGetSymbolAddress((void**)&p_v,    g_v);
    cudaGetSymbolAddress((void**)&p_x16,  g_x16);
    cudaGetSymbolAddress((void**)&p_at16, g_at16);
    cudaGetSymbolAddress((void**)&p_e16,  g_e16);
    cudaGetSymbolAddress((void**)&p_wq16, g_wq16);
    cudaGetSymbolAddress((void**)&p_wk16, g_wk16);
    cudaGetSymbolAddress((void**)&p_wv16, g_wv16);
    cudaGetSymbolAddress((void**)&p_wo16, g_wo16);

    cudaFuncSetAttribute(gemm_h<0, false>,
                         cudaFuncAttributeMaxDynamicSharedMemorySize, HGSMEM);
    cudaFuncSetAttribute(gemm_h<0, true>,
                         cudaFuncAttributeMaxDynamicSharedMemorySize, HGSMEM);
    cudaFuncSetAttribute(gemm_h<1, false>,
                         cudaFuncAttributeMaxDynamicSharedMemorySize, HGSMEM);
    cudaFuncSetAttribute(attn_mma,
                         cudaFuncAttributeMaxDynamicSharedMemorySize, AT_SMEM);

    // one-time fp16 conversions
    cvt_w_t<<<dim3(INNER / 32, CHN / 32), 256>>>(wq, p_wq16, CHN, INNER);
    cvt_w_t<<<dim3(INNER / 32, XDIM / 32), 256>>>(wk, p_wk16, XDIM, INNER);
    cvt_w_t<<<dim3(INNER / 32, XDIM / 32), 256>>>(wv, p_wv16, XDIM, INNER);
    cvt_w_t<<<dim3(CHN / 32, INNER / 32), 256>>>(wo, p_wo16, INNER, CHN);
    {
        int n = BATCH * TT * XDIM;
        cvt16<<<(n + 255) / 256, 256>>>(enc, p_e16, n);
    }

    // LN stats + normalize/transpose to fp16 [b][s][c]
    ln_stats<<<dim3(SP / 256, BATCH), 256>>>(hs);
    ln_t16<<<dim3(SP / 32, CHN / 32, BATCH), 256>>>(hs, lnw, lnb);

    // Q = x16 @ wq16^T
    gemm_h<0, false><<<dim3(INNER / 128, (BATCH * SP) / 128), 256, HGSMEM>>>(
        p_x16, p_wq16, p_q, BATCH * SP, INNER, CHN, CHN, nullptr, nullptr);

    // K, V = e16 @ w^T   (M = 1232, guarded)
    int mkv = (BATCH * TT + 127) / 128;
    gemm_h<0, true><<<dim3(INNER / 128, mkv), 256, HGSMEM>>>(
        p_e16, p_wk16, p_k, BATCH * TT, INNER, XDIM, XDIM, nullptr, nullptr);
    gemm_h<0, true><<<dim3(INNER / 128, mkv), 256, HGSMEM>>>(
        p_e16, p_wv16, p_v, BATCH * TT, INNER, XDIM, XDIM, nullptr, nullptr);

    // attention
    attn_mma<<<dim3(SP / 128, NHE, BATCH), 256, AT_SMEM>>>();

    // out = at16 @ wo16^T + bo + residual (transposed store)
    gemm_h<1, false><<<dim3(CHN / 128, (BATCH * SP) / 128), 256, HGSMEM>>>(
        p_at16, p_wo16, out, BATCH * SP, CHN, INNER, INNER, bo, hs);
}